// round 15
// baseline (speedup 1.0000x reference)
#include <cuda_runtime.h>
#include <cuda_bf16.h>
#include <stdint.h>
#include <math.h>

// ---------------- problem constants ----------------
#define BB   2
#define NN   512
#define HH   12
#define DHD  64
#define DIMD 768
#define DPR  128
#define DCND 512
#define INR  3072
#define NQ   32
#define NK   128
#define NWW  16
#define MROWS (BB*NN)    // 1024

// ---------------- fp32 scratch ----------------
#define OFF_COND  0L
#define OFF_XM    (OFF_COND + (long)MROWS*6*DIMD)
#define OFF_QKVG  (OFF_XM   + (long)MROWS*DIMD)
#define OFF_QR    (OFF_QKVG + (long)MROWS*4*DIMD)
#define OFF_KR    (OFF_QR   + (long)MROWS*DIMD)
#define OFF_VR    (OFF_KR   + (long)MROWS*DIMD)
#define OFF_BIAS  (OFF_VR   + (long)MROWS*DIMD)
#define OFF_X1    (OFF_BIAS + (long)BB*NWW*NQ*NK*HH)
#define OFF_AB    (OFF_X1   + (long)MROWS*DIMD)          // [a|g] fp32, 1024 x 6144
#define OFF_PART  (OFF_AB   + (long)MROWS*2*INR)
#define SCRATCH_TOTAL (OFF_PART + 3L*MROWS*DIMD)
__device__ float g_scratch[SCRATCH_TOTAL];

// ---------------- bf16 scratch: K-expanded operands (K' = 3K) ----------------
#define W2COND  0L                              // [1536][4608]
#define W2QKVG  (W2COND  + 1536L*4608)          // [2304][3072]
#define W2WO    (W2QKVG  + 2304L*3072)          // [2304][768]
#define W2TRIN  (W2WO    + 2304L*768)           // [2304][6144]
#define W2TROUT (W2TRIN  + 2304L*6144)          // [9216][768]
#define A2CN    (W2TROUT + 9216L*768)           // [1024][1536]
#define A2XA    (A2CN    + 1024L*1536)          // [1024][2304]
#define A2OG    (A2XA    + 1024L*2304)
#define A2XT    (A2OG    + 1024L*2304)
#define A2AB    (A2XT    + 1024L*2304)          // [1024][9216]
#define BF_TOTAL (A2AB   + 1024L*9216)
__device__ __nv_bfloat16 g_bf[BF_TOTAL];

__device__ __forceinline__ float sigf(float z) { return 1.f / (1.f + expf(-z)); }

__device__ __forceinline__ void bsplit(float v, __nv_bfloat16& hi, __nv_bfloat16& lo) {
    hi = __float2bfloat16_rn(v);
    lo = __float2bfloat16_rn(v - __bfloat162float(hi));
}
__device__ __forceinline__ void bsplit4(float4 w, uint2& hi4, uint2& lo4) {
    __nv_bfloat16 hx, hy, hz, hw, lx, ly, lz, lw;
    bsplit(w.x, hx, lx); bsplit(w.y, hy, ly);
    bsplit(w.z, hz, lz); bsplit(w.w, hw, lw);
    __nv_bfloat162 h01 = __nv_bfloat162(hx, hy), h23 = __nv_bfloat162(hz, hw);
    __nv_bfloat162 l01 = __nv_bfloat162(lx, ly), l23 = __nv_bfloat162(lz, lw);
    hi4.x = *(unsigned*)&h01; hi4.y = *(unsigned*)&h23;
    lo4.x = *(unsigned*)&l01; lo4.y = *(unsigned*)&l23;
}

// ---------------- block reduce ----------------
__device__ __forceinline__ float2 block_reduce2_256(float s, float s2) {
    __shared__ float shs[8], shq[8];
    int lane = threadIdx.x & 31, wp = threadIdx.x >> 5;
#pragma unroll
    for (int o = 16; o; o >>= 1) {
        s  += __shfl_xor_sync(0xffffffffu, s,  o);
        s2 += __shfl_xor_sync(0xffffffffu, s2, o);
    }
    if (lane == 0) { shs[wp] = s; shq[wp] = s2; }
    __syncthreads();
    if (wp == 0) {
        float a = (lane < 8) ? shs[lane] : 0.f;
        float b = (lane < 8) ? shq[lane] : 0.f;
#pragma unroll
        for (int o = 4; o; o >>= 1) {
            a += __shfl_xor_sync(0xffffffffu, a, o);
            b += __shfl_xor_sync(0xffffffffu, b, o);
        }
        if (lane == 0) { shs[0] = a; shq[0] = b; }
    }
    __syncthreads();
    return make_float2(shs[0], shq[0]);
}

// ---------------- LN(cond) -> decomposed bf16 [hi|lo|hi] ----------------
__global__ void ln_cond_kernel(const float* __restrict__ cond, __nv_bfloat16* __restrict__ out) {
    int m = blockIdx.x, t = threadIdx.x;
    const float* row = cond + (long)m * DCND;
    float v0 = row[t], v1 = row[t + 256];
    float2 r = block_reduce2_256(v0 + v1, v0 * v0 + v1 * v1);
    float mean = r.x * (1.f / DCND);
    float var  = r.y * (1.f / DCND) - mean * mean;
    float rstd = rsqrtf(var + 1e-5f);
    __nv_bfloat16* ob = out + (long)m * (3 * DCND);
#pragma unroll
    for (int i = 0; i < 2; i++) {
        int j = t + i * 256;
        float v = ((i ? v1 : v0) - mean) * rstd;
        __nv_bfloat16 hi, lo; bsplit(v, hi, lo);
        ob[j] = hi; ob[DCND + j] = lo; ob[2 * DCND + j] = hi;
    }
}

// ---------------- adaln1 -> decomposed bf16 (+ xm fp32) ----------------
__global__ void adaln_kernel(const float* __restrict__ xin, const float* __restrict__ mask,
                             const float* __restrict__ gatep, const float* __restrict__ shiftp,
                             float* __restrict__ xm_out, __nv_bfloat16* __restrict__ xa_bf) {
    int m = blockIdx.x, t = threadIdx.x;
    const float* row = xin + (long)m * DIMD;
    float mk = mask[m];
    float v[3];
#pragma unroll
    for (int i = 0; i < 3; i++) v[i] = row[t + i * 256] * mk;
    float s = 0.f, s2 = 0.f;
#pragma unroll
    for (int i = 0; i < 3; i++) { s += v[i]; s2 += v[i] * v[i]; }
    float2 r = block_reduce2_256(s, s2);
    float mean = r.x * (1.f / DIMD);
    float var  = r.y * (1.f / DIMD) - mean * mean;
    float rstd = rsqrtf(var + 1e-5f);
    __nv_bfloat16* ob = xa_bf + (long)m * (3 * DIMD);
#pragma unroll
    for (int i = 0; i < 3; i++) {
        int j = t + i * 256;
        xm_out[(long)m * DIMD + j] = v[i];
        float g = gatep[(long)m * (6 * DIMD) + j];
        float b = shiftp[(long)m * (6 * DIMD) + j];
        float val = ((v[i] - mean) * rstd * g + b) * mk;
        __nv_bfloat16 hi, lo; bsplit(val, hi, lo);
        ob[j] = hi; ob[DIMD + j] = lo; ob[2 * DIMD + j] = hi;
    }
}

// ---------------- per-head LN + RoPE ----------------
__global__ void qkrope_kernel(const float* __restrict__ qkvg,
                              float* __restrict__ qr, float* __restrict__ kr, float* __restrict__ vr) {
    int m = blockIdx.x;
    int b = m >> 9, n = m & 511;
    int h = threadIdx.x >> 5;
    int lane = threadIdx.x & 31;
    const float* base = qkvg + (long)m * (4 * DIMD) + h * DHD;
    long oo = ((long)(b * HH + h) * NN + n) * DHD;
    int p0 = lane >> 1, p1 = p0 + 16;
    const float kfac = 9.210340371976184f / 64.f;
    float ang0 = (float)n * expf(-(float)(2 * p0) * kfac);
    float ang1 = (float)n * expf(-(float)(2 * p1) * kfac);
    float c0 = cosf(ang0), s0 = sinf(ang0);
    float c1 = cosf(ang1), s1 = sinf(ang1);
    bool odd = (lane & 1);
#pragma unroll
    for (int which = 0; which < 2; which++) {
        const float* src = base + which * DIMD;
        float v0 = src[lane], v1 = src[lane + 32];
        float s = v0 + v1, sq = v0 * v0 + v1 * v1;
#pragma unroll
        for (int o = 16; o; o >>= 1) {
            s  += __shfl_xor_sync(0xffffffffu, s,  o);
            sq += __shfl_xor_sync(0xffffffffu, sq, o);
        }
        float mean = s * (1.f / DHD);
        float var  = sq * (1.f / DHD) - mean * mean;
        float rstd = rsqrtf(var + 1e-5f);
        v0 = (v0 - mean) * rstd;
        v1 = (v1 - mean) * rstd;
        float o0 = __shfl_xor_sync(0xffffffffu, v0, 1);
        float o1 = __shfl_xor_sync(0xffffffffu, v1, 1);
        float r0 = odd ? (o0 * s0 + v0 * c0) : (v0 * c0 - o0 * s0);
        float r1 = odd ? (o1 * s1 + v1 * c1) : (v1 * c1 - o1 * s1);
        float* dst = (which == 0) ? qr : kr;
        dst[oo + lane] = r0;
        dst[oo + lane + 32] = r1;
    }
    const float* vsrc = base + 2 * DIMD;
    vr[oo + lane] = vsrc[lane];
    vr[oo + lane + 32] = vsrc[lane + 32];
}

// ---------------- pair bias (windowed only) ----------------
__global__ void pairbias_kernel(const float* __restrict__ pair_rep, const float* __restrict__ wb,
                                float* __restrict__ biasw) {
    __shared__ float wbs[DPR * HH];
    __shared__ float colsum[HH];
    int t = threadIdx.x;
    for (int i = t; i < DPR * HH; i += 128) wbs[i] = wb[i];
    __syncthreads();
    if (t < HH) {
        float cs = 0.f;
        for (int p = 0; p < DPR; p++) cs += wbs[p * HH + t];
        colsum[t] = cs;
    }
    __syncthreads();
    int blk = blockIdx.x;
    int q = blk & 31, w = (blk >> 5) & 15, b = blk >> 9;
    int i = w * NQ + q;
    int idx = w * NQ - 48 + t;
    int j = min(max(idx, 0), NN - 1);
    const float* xr = pair_rep + (((long)b * NN + i) * NN + j) * DPR;
    float s = 0.f, s2 = 0.f;
    float dot[HH];
#pragma unroll
    for (int h = 0; h < HH; h++) dot[h] = 0.f;
#pragma unroll 4
    for (int p = 0; p < DPR; p += 4) {
        float4 xv = *(const float4*)(xr + p);
        s  += xv.x + xv.y + xv.z + xv.w;
        s2 += xv.x * xv.x + xv.y * xv.y + xv.z * xv.z + xv.w * xv.w;
#pragma unroll
        for (int h = 0; h < HH; h++)
            dot[h] += xv.x * wbs[p * HH + h] + xv.y * wbs[(p + 1) * HH + h]
                    + xv.z * wbs[(p + 2) * HH + h] + xv.w * wbs[(p + 3) * HH + h];
    }
    float mean = s * (1.f / DPR);
    float var  = s2 * (1.f / DPR) - mean * mean;
    float rstd = rsqrtf(var + 1e-5f);
    float* outp = biasw + ((long)blk * NK + t) * HH;
#pragma unroll
    for (int h = 0; h < HH; h++) outp[h] = (dot[h] - mean * colsum[h]) * rstd;
}

// ---------------- windowed attention -> decomposed og ----------------
__global__ __launch_bounds__(256) void attn_kernel(
    const float* __restrict__ qr, const float* __restrict__ kr, const float* __restrict__ vr,
    const float* __restrict__ pair_mask, const float* __restrict__ biasw,
    const float* __restrict__ qkvg, __nv_bfloat16* __restrict__ og_bf) {
    __shared__ float q_s[NQ][DHD];
    __shared__ float kv[64][65];
    __shared__ float sc[NQ][NK];
    int blk = blockIdx.x;
    int w = blk & 15;
    int h = (blk >> 4) % 12;
    int b = blk / 192;
    int t = threadIdx.x;
    long bh = (long)(b * HH + h) * NN * DHD;
    for (int e = t; e < NQ * DHD; e += 256) {
        int qq = e >> 6, d = e & 63;
        q_s[qq][d] = qr[bh + (long)(w * NQ + qq) * DHD + d];
    }
    int qrow = t >> 3, klane = t & 7;
    int iglob = w * NQ + qrow;
    for (int half = 0; half < 2; half++) {
        __syncthreads();
        for (int e = t; e < 64 * 64; e += 256) {
            int d = e & 63, kkl = e >> 6;
            int kk = half * 64 + kkl;
            int jn = min(max(w * NQ - 48 + kk, 0), NN - 1);
            kv[kkl][d] = kr[bh + (long)jn * DHD + d];
        }
        __syncthreads();
#pragma unroll
        for (int jj = 0; jj < 8; jj++) {
            int kkl = klane + jj * 8;
            int kk = half * 64 + kkl;
            float dot = 0.f;
#pragma unroll
            for (int d = 0; d < DHD; d++) dot = fmaf(q_s[qrow][d], kv[kkl][d], dot);
            int idxr = w * NQ - 48 + kk;
            bool valid = (idxr >= 0) && (idxr < NN);
            int jn = min(max(idxr, 0), NN - 1);
            float pm = pair_mask[((long)b * NN + iglob) * NN + jn];
            float bv = biasw[(((long)(b * NWW + w) * NQ + qrow) * NK + kk) * HH + h];
            sc[qrow][kk] = (valid && pm > 0.f) ? (dot * 0.125f + bv) : -1e9f;
        }
    }
    __syncthreads();
    {
        float vals[16];
        float mx = -3.4e38f;
#pragma unroll
        for (int jj = 0; jj < 16; jj++) {
            vals[jj] = sc[qrow][klane + jj * 8];
            mx = fmaxf(mx, vals[jj]);
        }
#pragma unroll
        for (int o = 4; o; o >>= 1) mx = fmaxf(mx, __shfl_xor_sync(0xffffffffu, mx, o));
        float sm = 0.f;
#pragma unroll
        for (int jj = 0; jj < 16; jj++) { vals[jj] = expf(vals[jj] - mx); sm += vals[jj]; }
#pragma unroll
        for (int o = 4; o; o >>= 1) sm += __shfl_xor_sync(0xffffffffu, sm, o);
        float inv = 1.f / sm;
#pragma unroll
        for (int jj = 0; jj < 16; jj++) sc[qrow][klane + jj * 8] = vals[jj] * inv;
    }
    int dgrp = t & 7;
    float outv[8];
#pragma unroll
    for (int jj = 0; jj < 8; jj++) outv[jj] = 0.f;
    for (int half = 0; half < 2; half++) {
        __syncthreads();
        for (int e = t; e < 64 * 64; e += 256) {
            int d = e & 63, kkl = e >> 6;
            int kk = half * 64 + kkl;
            int jn = min(max(w * NQ - 48 + kk, 0), NN - 1);
            kv[kkl][d] = vr[bh + (long)jn * DHD + d];
        }
        __syncthreads();
#pragma unroll 8
        for (int kkl = 0; kkl < 64; kkl++) {
            float a = sc[qrow][half * 64 + kkl];
#pragma unroll
            for (int jj = 0; jj < 8; jj++)
                outv[jj] = fmaf(a, kv[kkl][dgrp + jj * 8], outv[jj]);
        }
    }
    int m = b * NN + iglob;
    const float* gp = qkvg + (long)m * (4 * DIMD) + 3 * DIMD + h * DHD;
    __nv_bfloat16* ob = og_bf + (long)m * (3 * DIMD) + h * DHD;
#pragma unroll
    for (int jj = 0; jj < 8; jj++) {
        int d = dgrp + jj * 8;
        float v = outv[jj] * gp[d];
        __nv_bfloat16 hi, lo; bsplit(v, hi, lo);
        ob[d] = hi; ob[DIMD + d] = lo; ob[2 * DIMD + d] = hi;
    }
}

// ---------------- weight decompositions (job table), x8 vectorized ----------------
#define NJOBS 13
struct DWAll {
    const float* src[NJOBS];
    long dstoff[NJOBS];
    long base8[NJOBS + 1];
    int K[NJOBS], Nmat[NJOBS], Ntot[NJOBS], coloff[NJOBS];
};
__global__ void decomp_w_all_kernel(DWAll p, __nv_bfloat16* __restrict__ bf) {
    long idx8 = (long)blockIdx.x * 256 + threadIdx.x;
    int j = 0;
#pragma unroll
    for (int q = 0; q < NJOBS; q++) if (idx8 >= p.base8[q + 1]) j = q + 1;
    long e = (idx8 - p.base8[j]) * 8;
    int Nm = p.Nmat[j];
    int k = (int)(e / Nm);
    int n = (int)(e - (long)k * Nm);
    const float* sp = p.src[j] + e;
    float4 w0 = *(const float4*)sp;
    float4 w1 = *(const float4*)(sp + 4);
    uint4 hi8, lo8;
    { uint2 h, l; bsplit4(w0, h, l); hi8.x = h.x; hi8.y = h.y; lo8.x = l.x; lo8.y = l.y; }
    { uint2 h, l; bsplit4(w1, h, l); hi8.z = h.x; hi8.w = h.y; lo8.z = l.x; lo8.w = l.y; }
    long Nt = p.Ntot[j];
    long seg = (long)p.K[j] * Nt;
    __nv_bfloat16* d0 = bf + p.dstoff[j] + (long)k * Nt + p.coloff[j] + n;
    *(uint4*)d0             = hi8;
    *(uint4*)(d0 + seg)     = hi8;
    *(uint4*)(d0 + 2 * seg) = lo8;
}

// ---------------- tensor-core GEMM ----------------
__device__ __forceinline__ void mma_bf16(float* d, const unsigned* a, const unsigned* b) {
    asm volatile(
        "mma.sync.aligned.m16n8k16.row.col.f32.bf16.bf16.f32 "
        "{%0,%1,%2,%3}, {%4,%5,%6,%7}, {%8,%9}, {%0,%1,%2,%3};"
        : "+f"(d[0]), "+f"(d[1]), "+f"(d[2]), "+f"(d[3])
        : "r"(a[0]), "r"(a[1]), "r"(a[2]), "r"(a[3]), "r"(b[0]), "r"(b[1]));
}
__device__ __forceinline__ void ldsm_x4(unsigned* r, uint32_t addr) {
    asm volatile("ldmatrix.sync.aligned.m8n8.x4.shared.b16 {%0,%1,%2,%3}, [%4];"
                 : "=r"(r[0]), "=r"(r[1]), "=r"(r[2]), "=r"(r[3]) : "r"(addr));
}
__device__ __forceinline__ void ldsm_x2t(unsigned* r, uint32_t addr) {
    asm volatile("ldmatrix.sync.aligned.m8n8.x2.trans.shared.b16 {%0,%1}, [%2];"
                 : "=r"(r[0]), "=r"(r[1]) : "r"(addr));
}

struct MG {
    const __nv_bfloat16* A; int KE;
    const __nv_bfloat16* B; int Nld;
    float* C; int ldc;
    int M, Ntot;
    const float* biasp[6]; int sig[6]; int multi;
    int splitk;
};

#define KPA 40
#define BPA 136

__global__ void __launch_bounds__(256, 2) mma_gemm_kernel(MG p) {
    __shared__ __nv_bfloat16 As[2][128][KPA];
    __shared__ __nv_bfloat16 Bs[2][32][BPA];
    const int tid = threadIdx.x;
    const int lane = tid & 31, wid = tid >> 5;
    const int wm = wid & 3, wn = wid >> 2;
    const int row0 = blockIdx.y * 128, col0 = blockIdx.x * 128;
    const int Kper = p.KE / p.splitk;
    const int k0 = blockIdx.z * Kper;

    const int ar0 = tid >> 2, ac = (tid & 3) * 8;
    const int br0 = tid >> 4, bc = (tid & 15) * 8;
    const __nv_bfloat16* aptr0 = p.A + (long)(row0 + ar0) * p.KE + k0 + ac;
    const __nv_bfloat16* aptr1 = aptr0 + 64L * p.KE;
    const __nv_bfloat16* bptr0 = p.B + (long)(k0 + br0) * p.Nld + col0 + bc;
    const __nv_bfloat16* bptr1 = bptr0 + 16L * p.Nld;

    float acc[2][8][4];
#pragma unroll
    for (int i = 0; i < 2; i++)
#pragma unroll
        for (int j = 0; j < 8; j++)
#pragma unroll
            for (int q = 0; q < 4; q++) acc[i][j][q] = 0.f;

    const int nt = Kper / 32;
    uint4 fa0 = *(const uint4*)aptr0;
    uint4 fa1 = *(const uint4*)aptr1;
    uint4 fb0 = *(const uint4*)bptr0;
    uint4 fb1 = *(const uint4*)bptr1;
    *(uint4*)&As[0][ar0][ac]      = fa0;
    *(uint4*)&As[0][ar0 + 64][ac] = fa1;
    *(uint4*)&Bs[0][br0][bc]      = fb0;
    *(uint4*)&Bs[0][br0 + 16][bc] = fb1;
    __syncthreads();

    for (int t = 0; t < nt; t++) {
        const int buf = t & 1;
        if (t + 1 < nt) {
            fa0 = *(const uint4*)(aptr0 + (t + 1) * 32);
            fa1 = *(const uint4*)(aptr1 + (t + 1) * 32);
            fb0 = *(const uint4*)(bptr0 + (long)(t + 1) * 32 * p.Nld);
            fb1 = *(const uint4*)(bptr1 + (long)(t + 1) * 32 * p.Nld);
        }
#pragma unroll
        for (int ks = 0; ks < 2; ks++) {
            unsigned afr[2][4];
#pragma unroll
            for (int i = 0; i < 2; i++) {
                uint32_t ad = (uint32_t)__cvta_generic_to_shared(
                    &As[buf][wm * 32 + i * 16 + (lane & 15)][ks * 16 + (lane >> 4) * 8]);
                ldsm_x4(afr[i], ad);
            }
            unsigned bfr[8][2];
#pragma unroll
            for (int j = 0; j < 8; j++) {
                uint32_t bd = (uint32_t)__cvta_generic_to_shared(
                    &Bs[buf][ks * 16 + (lane & 15)][wn * 64 + j * 8]);
                ldsm_x2t(bfr[j], bd);
            }
#pragma unroll
            for (int i = 0; i < 2; i++)
#pragma unroll
                for (int j = 0; j < 8; j++)
                    mma_bf16(acc[i][j], afr[i], bfr[j]);
        }
        if (t + 1 < nt) {
            const int nb = buf ^ 1;
            *(uint4*)&As[nb][ar0][ac]      = fa0;
            *(uint4*)&As[nb][ar0 + 64][ac] = fa1;
            *(uint4*)&Bs[nb][br0][bc]      = fb0;
            *(uint4*)&Bs[nb][br0 + 16][bc] = fb1;
            __syncthreads();
        }
    }

    const int rbase = row0 + wm * 32 + (lane >> 2);
    const int cbase = col0 + wn * 64 + (lane & 3) * 2;
    if (p.splitk > 1) {
        float* Cp = p.C + (long)blockIdx.z * p.M * p.Ntot;
#pragma unroll
        for (int i = 0; i < 2; i++)
#pragma unroll
            for (int j = 0; j < 8; j++) {
                int r = rbase + i * 16, c = cbase + j * 8;
                *(float2*)(Cp + (long)r * p.Ntot + c)       = make_float2(acc[i][j][0], acc[i][j][1]);
                *(float2*)(Cp + (long)(r + 8) * p.Ntot + c) = make_float2(acc[i][j][2], acc[i][j][3]);
            }
    } else {
        int wblk = p.multi ? (col0 / 768) : 0;
        const float* bias = p.biasp[wblk];
        int dosig = p.sig[wblk];
        int noff = wblk * 768;
#pragma unroll
        for (int i = 0; i < 2; i++)
#pragma unroll
            for (int j = 0; j < 8; j++) {
                int r = rbase + i * 16, c = cbase + j * 8;
                float b0 = bias ? bias[c - noff] : 0.f;
                float b1 = bias ? bias[c + 1 - noff] : 0.f;
                float z0 = acc[i][j][0] + b0, z1 = acc[i][j][1] + b1;
                float z2 = acc[i][j][2] + b0, z3 = acc[i][j][3] + b1;
                if (dosig) { z0 = sigf(z0); z1 = sigf(z1); z2 = sigf(z2); z3 = sigf(z3); }
                *(float2*)(p.C + (long)r * p.ldc + c)       = make_float2(z0, z1);
                *(float2*)(p.C + (long)(r + 8) * p.ldc + c) = make_float2(z2, z3);
            }
    }
}

// ---------------- hidden = a * silu(g) -> decomposed bf16 ----------------
__global__ void silu_decomp_kernel(const float* __restrict__ ab, __nv_bfloat16* __restrict__ out) {
    long i = (long)blockIdx.x * 256 + threadIdx.x;
    int m = (int)(i / (INR / 4));
    int c4 = (int)(i % (INR / 4)) * 4;
    float4 a = *(const float4*)(ab + (long)m * (2 * INR) + c4);
    float4 g = *(const float4*)(ab + (long)m * (2 * INR) + INR + c4);
    float4 hv;
    hv.x = a.x * g.x * sigf(g.x);
    hv.y = a.y * g.y * sigf(g.y);
    hv.z = a.z * g.z * sigf(g.z);
    hv.w = a.w * g.w * sigf(g.w);
    uint2 hi4, lo4; bsplit4(hv, hi4, lo4);
    __nv_bfloat16* d0 = out + (long)m * (3 * INR) + c4;
    *(uint2*)d0             = hi4;
    *(uint2*)(d0 + INR)     = lo4;
    *(uint2*)(d0 + 2 * INR) = hi4;
}

// ---------------- fused: split-K reduce (wo) + scale1 + residual + adaln2 + decompose ----------------
__global__ void reduce_adaln_kernel(const float* __restrict__ part,
                                    const float* __restrict__ bias,
                                    const float* __restrict__ sig1,
                                    const float* __restrict__ g2,
                                    const float* __restrict__ b2,
                                    const float* __restrict__ xm,
                                    const float* __restrict__ mask,
                                    float* __restrict__ x1_out,
                                    __nv_bfloat16* __restrict__ xt_bf) {
    int m = blockIdx.x, t = threadIdx.x;
    float mk = mask[m];
    const long MN = (long)MROWS * DIMD;
    float v[3];
#pragma unroll
    for (int c = 0; c < 3; c++) {
        int n = t + c * 256;
        long idx = (long)m * DIMD + n;
        float z = part[idx] + part[MN + idx] + part[2 * MN + idx] + bias[n];
        float s = sig1[(long)m * (6 * DIMD) + n];
        float x1 = (z * s * mk * mk + xm[idx]) * mk;
        x1_out[idx] = x1;
        v[c] = x1;
    }
    float s = 0.f, s2 = 0.f;
#pragma unroll
    for (int c = 0; c < 3; c++) { s += v[c]; s2 += v[c] * v[c]; }
    float2 r = block_reduce2_256(s, s2);
    float mean = r.x * (1.f / DIMD);
    float var  = r.y * (1.f / DIMD) - mean * mean;
    float rstd = rsqrtf(var + 1e-5f);
    __nv_bfloat16* ob = xt_bf + (long)m * (3 * DIMD);
#pragma unroll
    for (int c = 0; c < 3; c++) {
        int j = t + c * 256;
        float g = g2[(long)m * (6 * DIMD) + j];
        float b = b2[(long)m * (6 * DIMD) + j];
        float val = ((v[c] - mean) * rstd * g + b) * mk;
        __nv_bfloat16 hi, lo; bsplit(val, hi, lo);
        ob[j] = hi; ob[DIMD + j] = lo; ob[2 * DIMD + j] = hi;
    }
}

// ---------------- final split-K reduce + epilogue ----------------
__global__ void reduce_epi_kernel(const float* __restrict__ part,
                                  const float* __restrict__ e1, int e1ld,
                                  const float* __restrict__ e2,
                                  const float* __restrict__ mask,
                                  float* __restrict__ C) {
    int m = blockIdx.x, t = threadIdx.x;
    float mk = mask[m];
    const long MN = (long)MROWS * DIMD;
#pragma unroll
    for (int c = 0; c < 3; c++) {
        int n = t + c * 256;
        long idx = (long)m * DIMD + n;
        float z = part[idx] + part[MN + idx] + part[2 * MN + idx];
        float s = e1[(long)m * e1ld + n];
        float t0 = z * mk;
        float t1 = t0 * s * mk * mk;
        C[idx] = ((t1 + e2[idx]) * mk) * mk;
    }
}

// ---------------- host launch ----------------
static void fill_jobs(DWAll& d, const float* const* srcs, const long* dsto,
                      const int* Ks, const int* Nm, const int* Nt, const int* Co,
                      int njobs, long& acc) {
    acc = 0;
    for (int j = 0; j < njobs; j++) {
        d.src[j] = srcs[j]; d.dstoff[j] = dsto[j];
        d.K[j] = Ks[j]; d.Nmat[j] = Nm[j]; d.Ntot[j] = Nt[j]; d.coloff[j] = Co[j];
        d.base8[j] = acc;
        acc += (long)Ks[j] * Nm[j] / 8;
    }
    for (int j = njobs; j <= NJOBS; j++) d.base8[j] = acc;
    for (int j = njobs; j < NJOBS; j++) {
        d.src[j] = srcs[njobs - 1]; d.dstoff[j] = dsto[njobs - 1];
        d.K[j] = Ks[njobs - 1]; d.Nmat[j] = Nm[njobs - 1];
        d.Ntot[j] = Nt[njobs - 1]; d.coloff[j] = Co[njobs - 1];
    }
}

extern "C" void kernel_launch(void* const* d_in, const int* in_sizes, int n_in,
                              void* d_out, int out_size) {
    const float* x         = (const float*)d_in[0];
    const float* pair_rep  = (const float*)d_in[1];
    const float* cond      = (const float*)d_in[2];
    const float* mask      = (const float*)d_in[3];
    const float* pair_mask = (const float*)d_in[4];
    const float* adaln1_gw = (const float*)d_in[5];
    const float* adaln1_gb = (const float*)d_in[6];
    const float* adaln1_bw = (const float*)d_in[7];
    const float* wq = (const float*)d_in[8],  *bq = (const float*)d_in[9];
    const float* wk = (const float*)d_in[10], *bk = (const float*)d_in[11];
    const float* wv = (const float*)d_in[12], *bv = (const float*)d_in[13];
    const float* wg = (const float*)d_in[14], *bg = (const float*)d_in[15];
    const float* wb_pair = (const float*)d_in[16];
    const float* wo = (const float*)d_in[17], *bo = (const float*)d_in[18];
    const float* scale1_w = (const float*)d_in[19], *scale1_b = (const float*)d_in[20];
    const float* adaln2_gw = (const float*)d_in[21], *adaln2_gb = (const float*)d_in[22];
    const float* adaln2_bw = (const float*)d_in[23];
    const float* tr_win  = (const float*)d_in[24];
    const float* tr_wout = (const float*)d_in[25];
    const float* scale2_w = (const float*)d_in[26], *scale2_b = (const float*)d_in[27];

    float* S = nullptr;
    cudaGetSymbolAddress((void**)&S, g_scratch);
    __nv_bfloat16* BF = nullptr;
    cudaGetSymbolAddress((void**)&BF, g_bf);

    float* cond_out = S + OFF_COND;
    float* xm       = S + OFF_XM;
    float* qkvg     = S + OFF_QKVG;
    float* qr       = S + OFF_QR;
    float* kr       = S + OFF_KR;
    float* vr       = S + OFF_VR;
    float* biasw    = S + OFF_BIAS;
    float* x1       = S + OFF_X1;
    float* ab       = S + OFF_AB;
    float* part     = S + OFF_PART;

    // side stream + fork/join events (host objects only; leaked — kernel_launch
    // runs a handful of times total, never during timing)
    cudaStream_t s2;
    cudaStreamCreateWithFlags(&s2, cudaStreamNonBlocking);
    cudaEvent_t evFork, evJoin;
    cudaEventCreateWithFlags(&evFork, cudaEventDisableTiming);
    cudaEventCreateWithFlags(&evJoin, cudaEventDisableTiming);

    // fork: side stream inherits capture
    cudaEventRecord(evFork, 0);
    cudaStreamWaitEvent(s2, evFork, 0);

    // ---- SIDE STREAM: late weight decomposition (wo, tr_win, tr_wout) + pair bias ----
    {
        DWAll d = {};
        const float* srcs[3] = { wo, tr_win, tr_wout };
        long  dsto[3] = { W2WO, W2TRIN, W2TROUT };
        int   Ks[3]   = { DIMD, DIMD, INR };
        int   Nm[3]   = { DIMD, 2 * INR, DIMD };
        int   Nt[3]   = { DIMD, 2 * INR, DIMD };
        int   Co[3]   = { 0, 0, 0 };
        long acc;
        fill_jobs(d, srcs, dsto, Ks, Nm, Nt, Co, 3, acc);
        decomp_w_all_kernel<<<(int)(acc / 256), 256, 0, s2>>>(d, BF);
    }
    pairbias_kernel<<<BB * NWW * NQ, 128, 0, s2>>>(pair_rep, wb_pair, biasw);
    cudaEventRecord(evJoin, s2);

    // ---- MAIN STREAM ----
    // early weight decomposition (cond projections + qkvg)
    {
        DWAll d = {};
        const float* srcs[10] = { adaln1_gw, adaln1_bw, scale1_w, adaln2_gw, adaln2_bw, scale2_w,
                                  wq, wk, wv, wg };
        long  dsto[10] = { W2COND, W2COND, W2COND, W2COND, W2COND, W2COND,
                           W2QKVG, W2QKVG, W2QKVG, W2QKVG };
        int   Ks[10]   = { DCND, DCND, DCND, DCND, DCND, DCND, DIMD, DIMD, DIMD, DIMD };
        int   Nm[10]   = { DIMD, DIMD, DIMD, DIMD, DIMD, DIMD, DIMD, DIMD, DIMD, DIMD };
        int   Nt[10]   = { 6 * DIMD, 6 * DIMD, 6 * DIMD, 6 * DIMD, 6 * DIMD, 6 * DIMD,
                           4 * DIMD, 4 * DIMD, 4 * DIMD, 4 * DIMD };
        int   Co[10]   = { 0, DIMD, 2 * DIMD, 3 * DIMD, 4 * DIMD, 5 * DIMD,
                           0, DIMD, 2 * DIMD, 3 * DIMD };
        long acc;
        fill_jobs(d, srcs, dsto, Ks, Nm, Nt, Co, 10, acc);
        decomp_w_all_kernel<<<(int)(acc / 256), 256>>>(d, BF);
    }

    // 1. LN(cond) -> bf16 decomposed
    ln_cond_kernel<<<MROWS, 256>>>(cond, BF + A2CN);

    // 2. six cond projections in one tensor GEMM
    {
        MG p = {};
        p.A = BF + A2CN; p.KE = 3 * DCND;
        p.B = BF + W2COND; p.Nld = 6 * DIMD;
        p.C = cond_out; p.ldc = 6 * DIMD; p.M = MROWS; p.Ntot = 6 * DIMD;
        p.biasp[0] = adaln1_gb; p.biasp[1] = nullptr; p.biasp[2] = scale1_b;
        p.biasp[3] = adaln2_gb; p.biasp[4] = nullptr; p.biasp[5] = scale2_b;
        p.sig[0] = 1; p.sig[1] = 0; p.sig[2] = 1; p.sig[3] = 1; p.sig[4] = 0; p.sig[5] = 1;
        p.multi = 1; p.splitk = 1;
        mma_gemm_kernel<<<dim3((6 * DIMD) / 128, MROWS / 128, 1), 256>>>(p);
    }

    // 3. xa = adaln1(x) -> bf16 decomposed (+ xm)
    adaln_kernel<<<MROWS, 256>>>(x, mask, cond_out, cond_out + DIMD, xm, BF + A2XA);

    // 4. QKVG tensor GEMM
    {
        MG p = {};
        p.A = BF + A2XA; p.KE = 3 * DIMD;
        p.B = BF + W2QKVG; p.Nld = 4 * DIMD;
        p.C = qkvg; p.ldc = 4 * DIMD; p.M = MROWS; p.Ntot = 4 * DIMD;
        p.biasp[0] = bq; p.biasp[1] = bk; p.biasp[2] = bv; p.biasp[3] = bg;
        p.sig[0] = 0; p.sig[1] = 0; p.sig[2] = 0; p.sig[3] = 1;
        p.multi = 1; p.splitk = 1;
        mma_gemm_kernel<<<dim3((4 * DIMD) / 128, MROWS / 128, 1), 256>>>(p);
    }

    // 5. rope
    qkrope_kernel<<<MROWS, 384>>>(qkvg, qr, kr, vr);

    // join side stream (pairbias + late weights ready)
    cudaStreamWaitEvent(0, evJoin, 0);

    // 6. attention
    attn_kernel<<<BB * HH * NWW, 256>>>(qr, kr, vr, pair_mask, biasw, qkvg, BF + A2OG);

    // 7. wo GEMM split-K=3 -> partials; fused reduce + scale1 + residual + adaln2 + decompose
    {
        MG p = {};
        p.A = BF + A2OG; p.KE = 3 * DIMD;
        p.B = BF + W2WO; p.Nld = DIMD;
        p.C = part; p.ldc = DIMD; p.M = MROWS; p.Ntot = DIMD;
        p.multi = 0; p.splitk = 3;
        mma_gemm_kernel<<<dim3(DIMD / 128, MROWS / 128, 3), 256>>>(p);
        reduce_adaln_kernel<<<MROWS, 256>>>(part, bo,
                                            cond_out + 2 * DIMD, cond_out + 3 * DIMD,
                                            cond_out + 4 * DIMD, xm, mask, x1, BF + A2XT);
    }

    // 8. merged transition-in [a|g] tensor GEMM
    {
        MG p = {};
        p.A = BF + A2XT; p.KE = 3 * DIMD;
        p.B = BF + W2TRIN; p.Nld = 2 * INR;
        p.C = ab; p.ldc = 2 * INR; p.M = MROWS; p.Ntot = 2 * INR;
        p.multi = 0; p.splitk = 1;
        mma_gemm_kernel<<<dim3((2 * INR) / 128, MROWS / 128, 1), 256>>>(p);
    }
    // 9. hidden = a * silu(g) -> bf16 decomposed
    silu_decomp_kernel<<<(int)((long)MROWS * INR / 4 / 256), 256>>>(ab, BF + A2AB);

    // 10. transition-out split-K=3 + reduce+epilogue -> d_out
    {
        MG p = {};
        p.A = BF + A2AB; p.KE = 3 * INR;
        p.B = BF + W2TROUT; p.Nld = DIMD;
        p.C = part; p.ldc = DIMD; p.M = MROWS; p.Ntot = DIMD;
        p.multi = 0; p.splitk = 3;
        mma_gemm_kernel<<<dim3(DIMD / 128, MROWS / 128, 3), 256>>>(p);
        reduce_epi_kernel<<<MROWS, 256>>>(part, cond_out + 5 * DIMD, 6 * DIMD,
                                          x1, mask, (float*)d_out);
    }
}

// round 16
// speedup vs baseline: 1.0310x; 1.0310x over previous
#include <cuda_runtime.h>
#include <cuda_bf16.h>
#include <stdint.h>
#include <math.h>

// ---------------- problem constants ----------------
#define BB   2
#define NN   512
#define HH   12
#define DHD  64
#define DIMD 768
#define DPR  128
#define DCND 512
#define INR  3072
#define NQ   32
#define NK   128
#define NWW  16
#define MROWS (BB*NN)    // 1024

// ---------------- fp32 scratch ----------------
#define OFF_COND  0L
#define OFF_XM    (OFF_COND + (long)MROWS*6*DIMD)
#define OFF_QKVG  (OFF_XM   + (long)MROWS*DIMD)
#define OFF_QR    (OFF_QKVG + (long)MROWS*4*DIMD)
#define OFF_KR    (OFF_QR   + (long)MROWS*DIMD)
#define OFF_VR    (OFF_KR   + (long)MROWS*DIMD)
#define OFF_BIAS  (OFF_VR   + (long)MROWS*DIMD)
#define OFF_X1    (OFF_BIAS + (long)BB*NWW*NQ*NK*HH)
#define OFF_AB    (OFF_X1   + (long)MROWS*DIMD)          // [a|g] fp32, 1024 x 6144
#define OFF_PART  (OFF_AB   + (long)MROWS*2*INR)
#define SCRATCH_TOTAL (OFF_PART + 3L*MROWS*DIMD)
__device__ float g_scratch[SCRATCH_TOTAL];

// ---------------- bf16 scratch: K-expanded operands (K' = 3K) ----------------
#define W2COND  0L                              // [1536][4608]
#define W2QKVG  (W2COND  + 1536L*4608)          // [2304][3072]
#define W2WO    (W2QKVG  + 2304L*3072)          // [2304][768]
#define W2TRIN  (W2WO    + 2304L*768)           // [2304][6144]
#define W2TROUT (W2TRIN  + 2304L*6144)          // [9216][768]
#define A2CN    (W2TROUT + 9216L*768)           // [1024][1536]
#define A2XA    (A2CN    + 1024L*1536)          // [1024][2304]
#define A2OG    (A2XA    + 1024L*2304)
#define A2XT    (A2OG    + 1024L*2304)
#define A2AB    (A2XT    + 1024L*2304)          // [1024][9216]
#define BF_TOTAL (A2AB   + 1024L*9216)
__device__ __nv_bfloat16 g_bf[BF_TOTAL];

__device__ __forceinline__ float sigf(float z) { return 1.f / (1.f + expf(-z)); }

__device__ __forceinline__ void bsplit(float v, __nv_bfloat16& hi, __nv_bfloat16& lo) {
    hi = __float2bfloat16_rn(v);
    lo = __float2bfloat16_rn(v - __bfloat162float(hi));
}
__device__ __forceinline__ void bsplit4(float4 w, uint2& hi4, uint2& lo4) {
    __nv_bfloat16 hx, hy, hz, hw, lx, ly, lz, lw;
    bsplit(w.x, hx, lx); bsplit(w.y, hy, ly);
    bsplit(w.z, hz, lz); bsplit(w.w, hw, lw);
    __nv_bfloat162 h01 = __nv_bfloat162(hx, hy), h23 = __nv_bfloat162(hz, hw);
    __nv_bfloat162 l01 = __nv_bfloat162(lx, ly), l23 = __nv_bfloat162(lz, lw);
    hi4.x = *(unsigned*)&h01; hi4.y = *(unsigned*)&h23;
    lo4.x = *(unsigned*)&l01; lo4.y = *(unsigned*)&l23;
}

// ---------------- block reduce ----------------
__device__ __forceinline__ float2 block_reduce2_256(float s, float s2) {
    __shared__ float shs[8], shq[8];
    int lane = threadIdx.x & 31, wp = threadIdx.x >> 5;
#pragma unroll
    for (int o = 16; o; o >>= 1) {
        s  += __shfl_xor_sync(0xffffffffu, s,  o);
        s2 += __shfl_xor_sync(0xffffffffu, s2, o);
    }
    if (lane == 0) { shs[wp] = s; shq[wp] = s2; }
    __syncthreads();
    if (wp == 0) {
        float a = (lane < 8) ? shs[lane] : 0.f;
        float b = (lane < 8) ? shq[lane] : 0.f;
#pragma unroll
        for (int o = 4; o; o >>= 1) {
            a += __shfl_xor_sync(0xffffffffu, a, o);
            b += __shfl_xor_sync(0xffffffffu, b, o);
        }
        if (lane == 0) { shs[0] = a; shq[0] = b; }
    }
    __syncthreads();
    return make_float2(shs[0], shq[0]);
}

// ---------------- LN(cond) -> decomposed bf16 [hi|lo|hi] ----------------
__global__ void ln_cond_kernel(const float* __restrict__ cond, __nv_bfloat16* __restrict__ out) {
    int m = blockIdx.x, t = threadIdx.x;
    const float* row = cond + (long)m * DCND;
    float v0 = row[t], v1 = row[t + 256];
    float2 r = block_reduce2_256(v0 + v1, v0 * v0 + v1 * v1);
    float mean = r.x * (1.f / DCND);
    float var  = r.y * (1.f / DCND) - mean * mean;
    float rstd = rsqrtf(var + 1e-5f);
    __nv_bfloat16* ob = out + (long)m * (3 * DCND);
#pragma unroll
    for (int i = 0; i < 2; i++) {
        int j = t + i * 256;
        float v = ((i ? v1 : v0) - mean) * rstd;
        __nv_bfloat16 hi, lo; bsplit(v, hi, lo);
        ob[j] = hi; ob[DCND + j] = lo; ob[2 * DCND + j] = hi;
    }
}

// ---------------- adaln1 -> decomposed bf16 (+ xm fp32) ----------------
__global__ void adaln_kernel(const float* __restrict__ xin, const float* __restrict__ mask,
                             const float* __restrict__ gatep, const float* __restrict__ shiftp,
                             float* __restrict__ xm_out, __nv_bfloat16* __restrict__ xa_bf) {
    int m = blockIdx.x, t = threadIdx.x;
    const float* row = xin + (long)m * DIMD;
    float mk = mask[m];
    float v[3];
#pragma unroll
    for (int i = 0; i < 3; i++) v[i] = row[t + i * 256] * mk;
    float s = 0.f, s2 = 0.f;
#pragma unroll
    for (int i = 0; i < 3; i++) { s += v[i]; s2 += v[i] * v[i]; }
    float2 r = block_reduce2_256(s, s2);
    float mean = r.x * (1.f / DIMD);
    float var  = r.y * (1.f / DIMD) - mean * mean;
    float rstd = rsqrtf(var + 1e-5f);
    __nv_bfloat16* ob = xa_bf + (long)m * (3 * DIMD);
#pragma unroll
    for (int i = 0; i < 3; i++) {
        int j = t + i * 256;
        xm_out[(long)m * DIMD + j] = v[i];
        float g = gatep[(long)m * (6 * DIMD) + j];
        float b = shiftp[(long)m * (6 * DIMD) + j];
        float val = ((v[i] - mean) * rstd * g + b) * mk;
        __nv_bfloat16 hi, lo; bsplit(val, hi, lo);
        ob[j] = hi; ob[DIMD + j] = lo; ob[2 * DIMD + j] = hi;
    }
}

// ---------------- per-head LN + RoPE ----------------
__global__ void qkrope_kernel(const float* __restrict__ qkvg,
                              float* __restrict__ qr, float* __restrict__ kr, float* __restrict__ vr) {
    int m = blockIdx.x;
    int b = m >> 9, n = m & 511;
    int h = threadIdx.x >> 5;
    int lane = threadIdx.x & 31;
    const float* base = qkvg + (long)m * (4 * DIMD) + h * DHD;
    long oo = ((long)(b * HH + h) * NN + n) * DHD;
    int p0 = lane >> 1, p1 = p0 + 16;
    const float kfac = 9.210340371976184f / 64.f;
    float ang0 = (float)n * expf(-(float)(2 * p0) * kfac);
    float ang1 = (float)n * expf(-(float)(2 * p1) * kfac);
    float c0 = cosf(ang0), s0 = sinf(ang0);
    float c1 = cosf(ang1), s1 = sinf(ang1);
    bool odd = (lane & 1);
#pragma unroll
    for (int which = 0; which < 2; which++) {
        const float* src = base + which * DIMD;
        float v0 = src[lane], v1 = src[lane + 32];
        float s = v0 + v1, sq = v0 * v0 + v1 * v1;
#pragma unroll
        for (int o = 16; o; o >>= 1) {
            s  += __shfl_xor_sync(0xffffffffu, s,  o);
            sq += __shfl_xor_sync(0xffffffffu, sq, o);
        }
        float mean = s * (1.f / DHD);
        float var  = sq * (1.f / DHD) - mean * mean;
        float rstd = rsqrtf(var + 1e-5f);
        v0 = (v0 - mean) * rstd;
        v1 = (v1 - mean) * rstd;
        float o0 = __shfl_xor_sync(0xffffffffu, v0, 1);
        float o1 = __shfl_xor_sync(0xffffffffu, v1, 1);
        float r0 = odd ? (o0 * s0 + v0 * c0) : (v0 * c0 - o0 * s0);
        float r1 = odd ? (o1 * s1 + v1 * c1) : (v1 * c1 - o1 * s1);
        float* dst = (which == 0) ? qr : kr;
        dst[oo + lane] = r0;
        dst[oo + lane + 32] = r1;
    }
    const float* vsrc = base + 2 * DIMD;
    vr[oo + lane] = vsrc[lane];
    vr[oo + lane + 32] = vsrc[lane + 32];
}

// ---------------- pair bias (windowed only) ----------------
__global__ void pairbias_kernel(const float* __restrict__ pair_rep, const float* __restrict__ wb,
                                float* __restrict__ biasw) {
    __shared__ float wbs[DPR * HH];
    __shared__ float colsum[HH];
    int t = threadIdx.x;
    for (int i = t; i < DPR * HH; i += 128) wbs[i] = wb[i];
    __syncthreads();
    if (t < HH) {
        float cs = 0.f;
        for (int p = 0; p < DPR; p++) cs += wbs[p * HH + t];
        colsum[t] = cs;
    }
    __syncthreads();
    int blk = blockIdx.x;
    int q = blk & 31, w = (blk >> 5) & 15, b = blk >> 9;
    int i = w * NQ + q;
    int idx = w * NQ - 48 + t;
    int j = min(max(idx, 0), NN - 1);
    const float* xr = pair_rep + (((long)b * NN + i) * NN + j) * DPR;
    float s = 0.f, s2 = 0.f;
    float dot[HH];
#pragma unroll
    for (int h = 0; h < HH; h++) dot[h] = 0.f;
#pragma unroll 4
    for (int p = 0; p < DPR; p += 4) {
        float4 xv = *(const float4*)(xr + p);
        s  += xv.x + xv.y + xv.z + xv.w;
        s2 += xv.x * xv.x + xv.y * xv.y + xv.z * xv.z + xv.w * xv.w;
#pragma unroll
        for (int h = 0; h < HH; h++)
            dot[h] += xv.x * wbs[p * HH + h] + xv.y * wbs[(p + 1) * HH + h]
                    + xv.z * wbs[(p + 2) * HH + h] + xv.w * wbs[(p + 3) * HH + h];
    }
    float mean = s * (1.f / DPR);
    float var  = s2 * (1.f / DPR) - mean * mean;
    float rstd = rsqrtf(var + 1e-5f);
    float* outp = biasw + ((long)blk * NK + t) * HH;
#pragma unroll
    for (int h = 0; h < HH; h++) outp[h] = (dot[h] - mean * colsum[h]) * rstd;
}

// ---------------- windowed attention -> decomposed og ----------------
__global__ __launch_bounds__(256) void attn_kernel(
    const float* __restrict__ qr, const float* __restrict__ kr, const float* __restrict__ vr,
    const float* __restrict__ pair_mask, const float* __restrict__ biasw,
    const float* __restrict__ qkvg, __nv_bfloat16* __restrict__ og_bf) {
    __shared__ float q_s[NQ][DHD];
    __shared__ float kv[64][65];
    __shared__ float sc[NQ][NK];
    int blk = blockIdx.x;
    int w = blk & 15;
    int h = (blk >> 4) % 12;
    int b = blk / 192;
    int t = threadIdx.x;
    long bh = (long)(b * HH + h) * NN * DHD;
    for (int e = t; e < NQ * DHD; e += 256) {
        int qq = e >> 6, d = e & 63;
        q_s[qq][d] = qr[bh + (long)(w * NQ + qq) * DHD + d];
    }
    int qrow = t >> 3, klane = t & 7;
    int iglob = w * NQ + qrow;
    for (int half = 0; half < 2; half++) {
        __syncthreads();
        for (int e = t; e < 64 * 64; e += 256) {
            int d = e & 63, kkl = e >> 6;
            int kk = half * 64 + kkl;
            int jn = min(max(w * NQ - 48 + kk, 0), NN - 1);
            kv[kkl][d] = kr[bh + (long)jn * DHD + d];
        }
        __syncthreads();
#pragma unroll
        for (int jj = 0; jj < 8; jj++) {
            int kkl = klane + jj * 8;
            int kk = half * 64 + kkl;
            float dot = 0.f;
#pragma unroll
            for (int d = 0; d < DHD; d++) dot = fmaf(q_s[qrow][d], kv[kkl][d], dot);
            int idxr = w * NQ - 48 + kk;
            bool valid = (idxr >= 0) && (idxr < NN);
            int jn = min(max(idxr, 0), NN - 1);
            float pm = pair_mask[((long)b * NN + iglob) * NN + jn];
            float bv = biasw[(((long)(b * NWW + w) * NQ + qrow) * NK + kk) * HH + h];
            sc[qrow][kk] = (valid && pm > 0.f) ? (dot * 0.125f + bv) : -1e9f;
        }
    }
    __syncthreads();
    {
        float vals[16];
        float mx = -3.4e38f;
#pragma unroll
        for (int jj = 0; jj < 16; jj++) {
            vals[jj] = sc[qrow][klane + jj * 8];
            mx = fmaxf(mx, vals[jj]);
        }
#pragma unroll
        for (int o = 4; o; o >>= 1) mx = fmaxf(mx, __shfl_xor_sync(0xffffffffu, mx, o));
        float sm = 0.f;
#pragma unroll
        for (int jj = 0; jj < 16; jj++) { vals[jj] = expf(vals[jj] - mx); sm += vals[jj]; }
#pragma unroll
        for (int o = 4; o; o >>= 1) sm += __shfl_xor_sync(0xffffffffu, sm, o);
        float inv = 1.f / sm;
#pragma unroll
        for (int jj = 0; jj < 16; jj++) sc[qrow][klane + jj * 8] = vals[jj] * inv;
    }
    int dgrp = t & 7;
    float outv[8];
#pragma unroll
    for (int jj = 0; jj < 8; jj++) outv[jj] = 0.f;
    for (int half = 0; half < 2; half++) {
        __syncthreads();
        for (int e = t; e < 64 * 64; e += 256) {
            int d = e & 63, kkl = e >> 6;
            int kk = half * 64 + kkl;
            int jn = min(max(w * NQ - 48 + kk, 0), NN - 1);
            kv[kkl][d] = vr[bh + (long)jn * DHD + d];
        }
        __syncthreads();
#pragma unroll 8
        for (int kkl = 0; kkl < 64; kkl++) {
            float a = sc[qrow][half * 64 + kkl];
#pragma unroll
            for (int jj = 0; jj < 8; jj++)
                outv[jj] = fmaf(a, kv[kkl][dgrp + jj * 8], outv[jj]);
        }
    }
    int m = b * NN + iglob;
    const float* gp = qkvg + (long)m * (4 * DIMD) + 3 * DIMD + h * DHD;
    __nv_bfloat16* ob = og_bf + (long)m * (3 * DIMD) + h * DHD;
#pragma unroll
    for (int jj = 0; jj < 8; jj++) {
        int d = dgrp + jj * 8;
        float v = outv[jj] * gp[d];
        __nv_bfloat16 hi, lo; bsplit(v, hi, lo);
        ob[d] = hi; ob[DIMD + d] = lo; ob[2 * DIMD + d] = hi;
    }
}

// ---------------- weight decompositions (job table), x8 vectorized ----------------
#define NJOBS 13
struct DWAll {
    const float* src[NJOBS];
    long dstoff[NJOBS];
    long base8[NJOBS + 1];
    int K[NJOBS], Nmat[NJOBS], Ntot[NJOBS], coloff[NJOBS];
};
__global__ void decomp_w_all_kernel(DWAll p, __nv_bfloat16* __restrict__ bf) {
    long idx8 = (long)blockIdx.x * 256 + threadIdx.x;
    int j = 0;
#pragma unroll
    for (int q = 0; q < NJOBS; q++) if (idx8 >= p.base8[q + 1]) j = q + 1;
    long e = (idx8 - p.base8[j]) * 8;
    int Nm = p.Nmat[j];
    int k = (int)(e / Nm);
    int n = (int)(e - (long)k * Nm);
    const float* sp = p.src[j] + e;
    float4 w0 = *(const float4*)sp;
    float4 w1 = *(const float4*)(sp + 4);
    uint4 hi8, lo8;
    { uint2 h, l; bsplit4(w0, h, l); hi8.x = h.x; hi8.y = h.y; lo8.x = l.x; lo8.y = l.y; }
    { uint2 h, l; bsplit4(w1, h, l); hi8.z = h.x; hi8.w = h.y; lo8.z = l.x; lo8.w = l.y; }
    long Nt = p.Ntot[j];
    long seg = (long)p.K[j] * Nt;
    __nv_bfloat16* d0 = bf + p.dstoff[j] + (long)k * Nt + p.coloff[j] + n;
    *(uint4*)d0             = hi8;
    *(uint4*)(d0 + seg)     = hi8;
    *(uint4*)(d0 + 2 * seg) = lo8;
}

// ---------------- tensor-core GEMM ----------------
__device__ __forceinline__ void mma_bf16(float* d, const unsigned* a, const unsigned* b) {
    asm volatile(
        "mma.sync.aligned.m16n8k16.row.col.f32.bf16.bf16.f32 "
        "{%0,%1,%2,%3}, {%4,%5,%6,%7}, {%8,%9}, {%0,%1,%2,%3};"
        : "+f"(d[0]), "+f"(d[1]), "+f"(d[2]), "+f"(d[3])
        : "r"(a[0]), "r"(a[1]), "r"(a[2]), "r"(a[3]), "r"(b[0]), "r"(b[1]));
}
__device__ __forceinline__ void ldsm_x4(unsigned* r, uint32_t addr) {
    asm volatile("ldmatrix.sync.aligned.m8n8.x4.shared.b16 {%0,%1,%2,%3}, [%4];"
                 : "=r"(r[0]), "=r"(r[1]), "=r"(r[2]), "=r"(r[3]) : "r"(addr));
}
__device__ __forceinline__ void ldsm_x4t(unsigned* r, uint32_t addr) {
    asm volatile("ldmatrix.sync.aligned.m8n8.x4.trans.shared.b16 {%0,%1,%2,%3}, [%4];"
                 : "=r"(r[0]), "=r"(r[1]), "=r"(r[2]), "=r"(r[3]) : "r"(addr));
}

struct MG {
    const __nv_bfloat16* A; int KE;
    const __nv_bfloat16* B; int Nld;
    float* C; int ldc;
    int M, Ntot;
    const float* biasp[6]; int sig[6]; int multi;
    int splitk;
};

#define KPA 40
#define BPA 136

__global__ void __launch_bounds__(256, 2) mma_gemm_kernel(MG p) {
    __shared__ __nv_bfloat16 As[2][128][KPA];
    __shared__ __nv_bfloat16 Bs[2][32][BPA];
    const int tid = threadIdx.x;
    const int lane = tid & 31, wid = tid >> 5;
    const int wm = wid & 3, wn = wid >> 2;
    const int row0 = blockIdx.y * 128, col0 = blockIdx.x * 128;
    const int Kper = p.KE / p.splitk;
    const int k0 = blockIdx.z * Kper;

    const int ar0 = tid >> 2, ac = (tid & 3) * 8;
    const int br0 = tid >> 4, bc = (tid & 15) * 8;
    const __nv_bfloat16* aptr0 = p.A + (long)(row0 + ar0) * p.KE + k0 + ac;
    const __nv_bfloat16* aptr1 = aptr0 + 64L * p.KE;
    const __nv_bfloat16* bptr0 = p.B + (long)(k0 + br0) * p.Nld + col0 + bc;
    const __nv_bfloat16* bptr1 = bptr0 + 16L * p.Nld;

    float acc[2][8][4];
#pragma unroll
    for (int i = 0; i < 2; i++)
#pragma unroll
        for (int j = 0; j < 8; j++)
#pragma unroll
            for (int q = 0; q < 4; q++) acc[i][j][q] = 0.f;

    const int nt = Kper / 32;
    uint4 fa0 = *(const uint4*)aptr0;
    uint4 fa1 = *(const uint4*)aptr1;
    uint4 fb0 = *(const uint4*)bptr0;
    uint4 fb1 = *(const uint4*)bptr1;
    *(uint4*)&As[0][ar0][ac]      = fa0;
    *(uint4*)&As[0][ar0 + 64][ac] = fa1;
    *(uint4*)&Bs[0][br0][bc]      = fb0;
    *(uint4*)&Bs[0][br0 + 16][bc] = fb1;
    __syncthreads();

    for (int t = 0; t < nt; t++) {
        const int buf = t & 1;
        if (t + 1 < nt) {
            fa0 = *(const uint4*)(aptr0 + (t + 1) * 32);
            fa1 = *(const uint4*)(aptr1 + (t + 1) * 32);
            fb0 = *(const uint4*)(bptr0 + (long)(t + 1) * 32 * p.Nld);
            fb1 = *(const uint4*)(bptr1 + (long)(t + 1) * 32 * p.Nld);
        }
#pragma unroll
        for (int ks = 0; ks < 2; ks++) {
            unsigned afr[2][4];
#pragma unroll
            for (int i = 0; i < 2; i++) {
                uint32_t ad = (uint32_t)__cvta_generic_to_shared(
                    &As[buf][wm * 32 + i * 16 + (lane & 15)][ks * 16 + (lane >> 4) * 8]);
                ldsm_x4(afr[i], ad);
            }
            // B: 4x ldmatrix.x4.trans, each covering k16 x n16
            // lanes 0-15: rows (k), col base; lanes 16-31: same rows, col base + 8
            unsigned bfr[8][2];
#pragma unroll
            for (int j = 0; j < 4; j++) {
                uint32_t bd = (uint32_t)__cvta_generic_to_shared(
                    &Bs[buf][ks * 16 + (lane & 15)][wn * 64 + j * 16 + ((lane >> 4) * 8)]);
                unsigned tmp[4];
                ldsm_x4t(tmp, bd);
                bfr[2 * j][0]     = tmp[0]; bfr[2 * j][1]     = tmp[1];
                bfr[2 * j + 1][0] = tmp[2]; bfr[2 * j + 1][1] = tmp[3];
            }
#pragma unroll
            for (int i = 0; i < 2; i++)
#pragma unroll
                for (int j = 0; j < 8; j++)
                    mma_bf16(acc[i][j], afr[i], bfr[j]);
        }
        if (t + 1 < nt) {
            const int nb = buf ^ 1;
            *(uint4*)&As[nb][ar0][ac]      = fa0;
            *(uint4*)&As[nb][ar0 + 64][ac] = fa1;
            *(uint4*)&Bs[nb][br0][bc]      = fb0;
            *(uint4*)&Bs[nb][br0 + 16][bc] = fb1;
            __syncthreads();
        }
    }

    const int rbase = row0 + wm * 32 + (lane >> 2);
    const int cbase = col0 + wn * 64 + (lane & 3) * 2;
    if (p.splitk > 1) {
        float* Cp = p.C + (long)blockIdx.z * p.M * p.Ntot;
#pragma unroll
        for (int i = 0; i < 2; i++)
#pragma unroll
            for (int j = 0; j < 8; j++) {
                int r = rbase + i * 16, c = cbase + j * 8;
                *(float2*)(Cp + (long)r * p.Ntot + c)       = make_float2(acc[i][j][0], acc[i][j][1]);
                *(float2*)(Cp + (long)(r + 8) * p.Ntot + c) = make_float2(acc[i][j][2], acc[i][j][3]);
            }
    } else {
        int wblk = p.multi ? (col0 / 768) : 0;
        const float* bias = p.biasp[wblk];
        int dosig = p.sig[wblk];
        int noff = wblk * 768;
#pragma unroll
        for (int i = 0; i < 2; i++)
#pragma unroll
            for (int j = 0; j < 8; j++) {
                int r = rbase + i * 16, c = cbase + j * 8;
                float b0 = bias ? bias[c - noff] : 0.f;
                float b1 = bias ? bias[c + 1 - noff] : 0.f;
                float z0 = acc[i][j][0] + b0, z1 = acc[i][j][1] + b1;
                float z2 = acc[i][j][2] + b0, z3 = acc[i][j][3] + b1;
                if (dosig) { z0 = sigf(z0); z1 = sigf(z1); z2 = sigf(z2); z3 = sigf(z3); }
                *(float2*)(p.C + (long)r * p.ldc + c)       = make_float2(z0, z1);
                *(float2*)(p.C + (long)(r + 8) * p.ldc + c) = make_float2(z2, z3);
            }
    }
}

// ---------------- hidden = a * silu(g) -> decomposed bf16 ----------------
__global__ void silu_decomp_kernel(const float* __restrict__ ab, __nv_bfloat16* __restrict__ out) {
    long i = (long)blockIdx.x * 256 + threadIdx.x;
    int m = (int)(i / (INR / 4));
    int c4 = (int)(i % (INR / 4)) * 4;
    float4 a = *(const float4*)(ab + (long)m * (2 * INR) + c4);
    float4 g = *(const float4*)(ab + (long)m * (2 * INR) + INR + c4);
    float4 hv;
    hv.x = a.x * g.x * sigf(g.x);
    hv.y = a.y * g.y * sigf(g.y);
    hv.z = a.z * g.z * sigf(g.z);
    hv.w = a.w * g.w * sigf(g.w);
    uint2 hi4, lo4; bsplit4(hv, hi4, lo4);
    __nv_bfloat16* d0 = out + (long)m * (3 * INR) + c4;
    *(uint2*)d0             = hi4;
    *(uint2*)(d0 + INR)     = lo4;
    *(uint2*)(d0 + 2 * INR) = hi4;
}

// ---------------- fused: split-K reduce (wo) + scale1 + residual + adaln2 + decompose ----------------
__global__ void reduce_adaln_kernel(const float* __restrict__ part,
                                    const float* __restrict__ bias,
                                    const float* __restrict__ sig1,
                                    const float* __restrict__ g2,
                                    const float* __restrict__ b2,
                                    const float* __restrict__ xm,
                                    const float* __restrict__ mask,
                                    float* __restrict__ x1_out,
                                    __nv_bfloat16* __restrict__ xt_bf) {
    int m = blockIdx.x, t = threadIdx.x;
    float mk = mask[m];
    const long MN = (long)MROWS * DIMD;
    float v[3];
#pragma unroll
    for (int c = 0; c < 3; c++) {
        int n = t + c * 256;
        long idx = (long)m * DIMD + n;
        float z = part[idx] + part[MN + idx] + part[2 * MN + idx] + bias[n];
        float s = sig1[(long)m * (6 * DIMD) + n];
        float x1 = (z * s * mk * mk + xm[idx]) * mk;
        x1_out[idx] = x1;
        v[c] = x1;
    }
    float s = 0.f, s2 = 0.f;
#pragma unroll
    for (int c = 0; c < 3; c++) { s += v[c]; s2 += v[c] * v[c]; }
    float2 r = block_reduce2_256(s, s2);
    float mean = r.x * (1.f / DIMD);
    float var  = r.y * (1.f / DIMD) - mean * mean;
    float rstd = rsqrtf(var + 1e-5f);
    __nv_bfloat16* ob = xt_bf + (long)m * (3 * DIMD);
#pragma unroll
    for (int c = 0; c < 3; c++) {
        int j = t + c * 256;
        float g = g2[(long)m * (6 * DIMD) + j];
        float b = b2[(long)m * (6 * DIMD) + j];
        float val = ((v[c] - mean) * rstd * g + b) * mk;
        __nv_bfloat16 hi, lo; bsplit(val, hi, lo);
        ob[j] = hi; ob[DIMD + j] = lo; ob[2 * DIMD + j] = hi;
    }
}

// ---------------- final split-K reduce + epilogue ----------------
__global__ void reduce_epi_kernel(const float* __restrict__ part,
                                  const float* __restrict__ e1, int e1ld,
                                  const float* __restrict__ e2,
                                  const float* __restrict__ mask,
                                  float* __restrict__ C) {
    int m = blockIdx.x, t = threadIdx.x;
    float mk = mask[m];
    const long MN = (long)MROWS * DIMD;
#pragma unroll
    for (int c = 0; c < 3; c++) {
        int n = t + c * 256;
        long idx = (long)m * DIMD + n;
        float z = part[idx] + part[MN + idx] + part[2 * MN + idx];
        float s = e1[(long)m * e1ld + n];
        float t0 = z * mk;
        float t1 = t0 * s * mk * mk;
        C[idx] = ((t1 + e2[idx]) * mk) * mk;
    }
}

// ---------------- host launch ----------------
static void fill_jobs(DWAll& d, const float* const* srcs, const long* dsto,
                      const int* Ks, const int* Nm, const int* Nt, const int* Co,
                      int njobs, long& acc) {
    acc = 0;
    for (int j = 0; j < njobs; j++) {
        d.src[j] = srcs[j]; d.dstoff[j] = dsto[j];
        d.K[j] = Ks[j]; d.Nmat[j] = Nm[j]; d.Ntot[j] = Nt[j]; d.coloff[j] = Co[j];
        d.base8[j] = acc;
        acc += (long)Ks[j] * Nm[j] / 8;
    }
    for (int j = njobs; j <= NJOBS; j++) d.base8[j] = acc;
    for (int j = njobs; j < NJOBS; j++) {
        d.src[j] = srcs[njobs - 1]; d.dstoff[j] = dsto[njobs - 1];
        d.K[j] = Ks[njobs - 1]; d.Nmat[j] = Nm[njobs - 1];
        d.Ntot[j] = Nt[njobs - 1]; d.coloff[j] = Co[njobs - 1];
    }
}

extern "C" void kernel_launch(void* const* d_in, const int* in_sizes, int n_in,
                              void* d_out, int out_size) {
    const float* x         = (const float*)d_in[0];
    const float* pair_rep  = (const float*)d_in[1];
    const float* cond      = (const float*)d_in[2];
    const float* mask      = (const float*)d_in[3];
    const float* pair_mask = (const float*)d_in[4];
    const float* adaln1_gw = (const float*)d_in[5];
    const float* adaln1_gb = (const float*)d_in[6];
    const float* adaln1_bw = (const float*)d_in[7];
    const float* wq = (const float*)d_in[8],  *bq = (const float*)d_in[9];
    const float* wk = (const float*)d_in[10], *bk = (const float*)d_in[11];
    const float* wv = (const float*)d_in[12], *bv = (const float*)d_in[13];
    const float* wg = (const float*)d_in[14], *bg = (const float*)d_in[15];
    const float* wb_pair = (const float*)d_in[16];
    const float* wo = (const float*)d_in[17], *bo = (const float*)d_in[18];
    const float* scale1_w = (const float*)d_in[19], *scale1_b = (const float*)d_in[20];
    const float* adaln2_gw = (const float*)d_in[21], *adaln2_gb = (const float*)d_in[22];
    const float* adaln2_bw = (const float*)d_in[23];
    const float* tr_win  = (const float*)d_in[24];
    const float* tr_wout = (const float*)d_in[25];
    const float* scale2_w = (const float*)d_in[26], *scale2_b = (const float*)d_in[27];

    float* S = nullptr;
    cudaGetSymbolAddress((void**)&S, g_scratch);
    __nv_bfloat16* BF = nullptr;
    cudaGetSymbolAddress((void**)&BF, g_bf);

    float* cond_out = S + OFF_COND;
    float* xm       = S + OFF_XM;
    float* qkvg     = S + OFF_QKVG;
    float* qr       = S + OFF_QR;
    float* kr       = S + OFF_KR;
    float* vr       = S + OFF_VR;
    float* biasw    = S + OFF_BIAS;
    float* x1       = S + OFF_X1;
    float* ab       = S + OFF_AB;
    float* part     = S + OFF_PART;

    // (1) early weight decomposition (cond projections + qkvg)
    {
        DWAll d = {};
        const float* srcs[10] = { adaln1_gw, adaln1_bw, scale1_w, adaln2_gw, adaln2_bw, scale2_w,
                                  wq, wk, wv, wg };
        long  dsto[10] = { W2COND, W2COND, W2COND, W2COND, W2COND, W2COND,
                           W2QKVG, W2QKVG, W2QKVG, W2QKVG };
        int   Ks[10]   = { DCND, DCND, DCND, DCND, DCND, DCND, DIMD, DIMD, DIMD, DIMD };
        int   Nm[10]   = { DIMD, DIMD, DIMD, DIMD, DIMD, DIMD, DIMD, DIMD, DIMD, DIMD };
        int   Nt[10]   = { 6 * DIMD, 6 * DIMD, 6 * DIMD, 6 * DIMD, 6 * DIMD, 6 * DIMD,
                           4 * DIMD, 4 * DIMD, 4 * DIMD, 4 * DIMD };
        int   Co[10]   = { 0, DIMD, 2 * DIMD, 3 * DIMD, 4 * DIMD, 5 * DIMD,
                           0, DIMD, 2 * DIMD, 3 * DIMD };
        long acc;
        fill_jobs(d, srcs, dsto, Ks, Nm, Nt, Co, 10, acc);
        decomp_w_all_kernel<<<(int)(acc / 256), 256>>>(d, BF);
    }

    // (2) LN(cond) -> bf16 decomposed
    ln_cond_kernel<<<MROWS, 256>>>(cond, BF + A2CN);

    // (3) late weight decomposition (wo, tr_win, tr_wout)
    {
        DWAll d = {};
        const float* srcs[3] = { wo, tr_win, tr_wout };
        long  dsto[3] = { W2WO, W2TRIN, W2TROUT };
        int   Ks[3]   = { DIMD, DIMD, INR };
        int   Nm[3]   = { DIMD, 2 * INR, DIMD };
        int   Nt[3]   = { DIMD, 2 * INR, DIMD };
        int   Co[3]   = { 0, 0, 0 };
        long acc;
        fill_jobs(d, srcs, dsto, Ks, Nm, Nt, Co, 3, acc);
        decomp_w_all_kernel<<<(int)(acc / 256), 256>>>(d, BF);
    }

    // (4) six cond projections in one tensor GEMM  <-- ncu capture target
    {
        MG p = {};
        p.A = BF + A2CN; p.KE = 3 * DCND;
        p.B = BF + W2COND; p.Nld = 6 * DIMD;
        p.C = cond_out; p.ldc = 6 * DIMD; p.M = MROWS; p.Ntot = 6 * DIMD;
        p.biasp[0] = adaln1_gb; p.biasp[1] = nullptr; p.biasp[2] = scale1_b;
        p.biasp[3] = adaln2_gb; p.biasp[4] = nullptr; p.biasp[5] = scale2_b;
        p.sig[0] = 1; p.sig[1] = 0; p.sig[2] = 1; p.sig[3] = 1; p.sig[4] = 0; p.sig[5] = 1;
        p.multi = 1; p.splitk = 1;
        mma_gemm_kernel<<<dim3((6 * DIMD) / 128, MROWS / 128, 1), 256>>>(p);
    }

    // (5) pair bias
    pairbias_kernel<<<BB * NWW * NQ, 128>>>(pair_rep, wb_pair, biasw);

    // (6) xa = adaln1(x) -> bf16 decomposed (+ xm)
    adaln_kernel<<<MROWS, 256>>>(x, mask, cond_out, cond_out + DIMD, xm, BF + A2XA);

    // (7) QKVG tensor GEMM
    {
        MG p = {};
        p.A = BF + A2XA; p.KE = 3 * DIMD;
        p.B = BF + W2QKVG; p.Nld = 4 * DIMD;
        p.C = qkvg; p.ldc = 4 * DIMD; p.M = MROWS; p.Ntot = 4 * DIMD;
        p.biasp[0] = bq; p.biasp[1] = bk; p.biasp[2] = bv; p.biasp[3] = bg;
        p.sig[0] = 0; p.sig[1] = 0; p.sig[2] = 0; p.sig[3] = 1;
        p.multi = 1; p.splitk = 1;
        mma_gemm_kernel<<<dim3((4 * DIMD) / 128, MROWS / 128, 1), 256>>>(p);
    }

    // (8) rope
    qkrope_kernel<<<MROWS, 384>>>(qkvg, qr, kr, vr);

    // (9) attention
    attn_kernel<<<BB * HH * NWW, 256>>>(qr, kr, vr, pair_mask, biasw, qkvg, BF + A2OG);

    // (10) wo GEMM split-K=3 -> partials; fused reduce + scale1 + residual + adaln2 + decompose
    {
        MG p = {};
        p.A = BF + A2OG; p.KE = 3 * DIMD;
        p.B = BF + W2WO; p.Nld = DIMD;
        p.C = part; p.ldc = DIMD; p.M = MROWS; p.Ntot = DIMD;
        p.multi = 0; p.splitk = 3;
        mma_gemm_kernel<<<dim3(DIMD / 128, MROWS / 128, 3), 256>>>(p);
        reduce_adaln_kernel<<<MROWS, 256>>>(part, bo,
                                            cond_out + 2 * DIMD, cond_out + 3 * DIMD,
                                            cond_out + 4 * DIMD, xm, mask, x1, BF + A2XT);
    }

    // (11) merged transition-in [a|g] tensor GEMM
    {
        MG p = {};
        p.A = BF + A2XT; p.KE = 3 * DIMD;
        p.B = BF + W2TRIN; p.Nld = 2 * INR;
        p.C = ab; p.ldc = 2 * INR; p.M = MROWS; p.Ntot = 2 * INR;
        p.multi = 0; p.splitk = 1;
        mma_gemm_kernel<<<dim3((2 * INR) / 128, MROWS / 128, 1), 256>>>(p);
    }
    // (12) hidden = a * silu(g) -> bf16 decomposed
    silu_decomp_kernel<<<(int)((long)MROWS * INR / 4 / 256), 256>>>(ab, BF + A2AB);

    // (13) transition-out split-K=3 + reduce+epilogue -> d_out
    {
        MG p = {};
        p.A = BF + A2AB; p.KE = 3 * INR;
        p.B = BF + W2TROUT; p.Nld = DIMD;
        p.C = part; p.ldc = DIMD; p.M = MROWS; p.Ntot = DIMD;
        p.multi = 0; p.splitk = 3;
        mma_gemm_kernel<<<dim3(DIMD / 128, MROWS / 128, 3), 256>>>(p);
        reduce_epi_kernel<<<MROWS, 256>>>(part, cond_out + 5 * DIMD, 6 * DIMD,
                                          x1, mask, (float*)d_out);
    }
}

// round 17
// speedup vs baseline: 1.1473x; 1.1128x over previous
#include <cuda_runtime.h>
#include <cuda_bf16.h>
#include <stdint.h>
#include <math.h>

// ---------------- problem constants ----------------
#define BB   2
#define NN   512
#define HH   12
#define DHD  64
#define DIMD 768
#define DPR  128
#define DCND 512
#define INR  3072
#define NQ   32
#define NK   128
#define NWW  16
#define MROWS (BB*NN)    // 1024

// ---------------- fp32 scratch ----------------
#define OFF_COND  0L
#define OFF_XM    (OFF_COND + (long)MROWS*6*DIMD)
#define OFF_QKVG  (OFF_XM   + (long)MROWS*DIMD)
#define OFF_QR    (OFF_QKVG + (long)MROWS*4*DIMD)
#define OFF_KR    (OFF_QR   + (long)MROWS*DIMD)
#define OFF_VR    (OFF_KR   + (long)MROWS*DIMD)
#define OFF_BIAS  (OFF_VR   + (long)MROWS*DIMD)
#define OFF_X1    (OFF_BIAS + (long)BB*NWW*NQ*NK*HH)
#define OFF_AB    (OFF_X1   + (long)MROWS*DIMD)          // [a|g] fp32, 1024 x 6144
#define OFF_PART  (OFF_AB   + (long)MROWS*2*INR)
#define SCRATCH_TOTAL (OFF_PART + 3L*MROWS*DIMD)
__device__ float g_scratch[SCRATCH_TOTAL];

// ---------------- bf16 scratch: [hi|lo] operands (K' = 2K) ----------------
#define W2COND  0L                              // [1024][4608]
#define W2QKVG  (W2COND  + 1024L*4608)          // [1536][3072]
#define W2WO    (W2QKVG  + 1536L*3072)          // [1536][768]
#define W2TRIN  (W2WO    + 1536L*768)           // [1536][6144]
#define W2TROUT (W2TRIN  + 1536L*6144)          // [6144][768]
#define A2CN    (W2TROUT + 6144L*768)           // [1024][1024]
#define A2XA    (A2CN    + 1024L*1024)          // [1024][1536]
#define A2OG    (A2XA    + 1024L*1536)
#define A2XT    (A2OG    + 1024L*1536)
#define A2AB    (A2XT    + 1024L*1536)          // [1024][6144]
#define BF_TOTAL (A2AB   + 1024L*6144)
__device__ __nv_bfloat16 g_bf[BF_TOTAL];

__device__ __forceinline__ float sigf(float z) { return 1.f / (1.f + expf(-z)); }

__device__ __forceinline__ void bsplit(float v, __nv_bfloat16& hi, __nv_bfloat16& lo) {
    hi = __float2bfloat16_rn(v);
    lo = __float2bfloat16_rn(v - __bfloat162float(hi));
}
__device__ __forceinline__ void bsplit4(float4 w, uint2& hi4, uint2& lo4) {
    __nv_bfloat16 hx, hy, hz, hw, lx, ly, lz, lw;
    bsplit(w.x, hx, lx); bsplit(w.y, hy, ly);
    bsplit(w.z, hz, lz); bsplit(w.w, hw, lw);
    __nv_bfloat162 h01 = __nv_bfloat162(hx, hy), h23 = __nv_bfloat162(hz, hw);
    __nv_bfloat162 l01 = __nv_bfloat162(lx, ly), l23 = __nv_bfloat162(lz, lw);
    hi4.x = *(unsigned*)&h01; hi4.y = *(unsigned*)&h23;
    lo4.x = *(unsigned*)&l01; lo4.y = *(unsigned*)&l23;
}

// ---------------- block reduce ----------------
__device__ __forceinline__ float2 block_reduce2_256(float s, float s2) {
    __shared__ float shs[8], shq[8];
    int lane = threadIdx.x & 31, wp = threadIdx.x >> 5;
#pragma unroll
    for (int o = 16; o; o >>= 1) {
        s  += __shfl_xor_sync(0xffffffffu, s,  o);
        s2 += __shfl_xor_sync(0xffffffffu, s2, o);
    }
    if (lane == 0) { shs[wp] = s; shq[wp] = s2; }
    __syncthreads();
    if (wp == 0) {
        float a = (lane < 8) ? shs[lane] : 0.f;
        float b = (lane < 8) ? shq[lane] : 0.f;
#pragma unroll
        for (int o = 4; o; o >>= 1) {
            a += __shfl_xor_sync(0xffffffffu, a, o);
            b += __shfl_xor_sync(0xffffffffu, b, o);
        }
        if (lane == 0) { shs[0] = a; shq[0] = b; }
    }
    __syncthreads();
    return make_float2(shs[0], shq[0]);
}

// ---------------- LN(cond) -> bf16 [hi|lo] ----------------
__global__ void ln_cond_kernel(const float* __restrict__ cond, __nv_bfloat16* __restrict__ out) {
    int m = blockIdx.x, t = threadIdx.x;
    const float* row = cond + (long)m * DCND;
    float v0 = row[t], v1 = row[t + 256];
    float2 r = block_reduce2_256(v0 + v1, v0 * v0 + v1 * v1);
    float mean = r.x * (1.f / DCND);
    float var  = r.y * (1.f / DCND) - mean * mean;
    float rstd = rsqrtf(var + 1e-5f);
    __nv_bfloat16* ob = out + (long)m * (2 * DCND);
#pragma unroll
    for (int i = 0; i < 2; i++) {
        int j = t + i * 256;
        float v = ((i ? v1 : v0) - mean) * rstd;
        __nv_bfloat16 hi, lo; bsplit(v, hi, lo);
        ob[j] = hi; ob[DCND + j] = lo;
    }
}

// ---------------- adaln1 -> bf16 [hi|lo] (+ xm fp32) ----------------
__global__ void adaln_kernel(const float* __restrict__ xin, const float* __restrict__ mask,
                             const float* __restrict__ gatep, const float* __restrict__ shiftp,
                             float* __restrict__ xm_out, __nv_bfloat16* __restrict__ xa_bf) {
    int m = blockIdx.x, t = threadIdx.x;
    const float* row = xin + (long)m * DIMD;
    float mk = mask[m];
    float v[3];
#pragma unroll
    for (int i = 0; i < 3; i++) v[i] = row[t + i * 256] * mk;
    float s = 0.f, s2 = 0.f;
#pragma unroll
    for (int i = 0; i < 3; i++) { s += v[i]; s2 += v[i] * v[i]; }
    float2 r = block_reduce2_256(s, s2);
    float mean = r.x * (1.f / DIMD);
    float var  = r.y * (1.f / DIMD) - mean * mean;
    float rstd = rsqrtf(var + 1e-5f);
    __nv_bfloat16* ob = xa_bf + (long)m * (2 * DIMD);
#pragma unroll
    for (int i = 0; i < 3; i++) {
        int j = t + i * 256;
        xm_out[(long)m * DIMD + j] = v[i];
        float g = gatep[(long)m * (6 * DIMD) + j];
        float b = shiftp[(long)m * (6 * DIMD) + j];
        float val = ((v[i] - mean) * rstd * g + b) * mk;
        __nv_bfloat16 hi, lo; bsplit(val, hi, lo);
        ob[j] = hi; ob[DIMD + j] = lo;
    }
}

// ---------------- per-head LN + RoPE ----------------
__global__ void qkrope_kernel(const float* __restrict__ qkvg,
                              float* __restrict__ qr, float* __restrict__ kr, float* __restrict__ vr) {
    int m = blockIdx.x;
    int b = m >> 9, n = m & 511;
    int h = threadIdx.x >> 5;
    int lane = threadIdx.x & 31;
    const float* base = qkvg + (long)m * (4 * DIMD) + h * DHD;
    long oo = ((long)(b * HH + h) * NN + n) * DHD;
    int p0 = lane >> 1, p1 = p0 + 16;
    const float kfac = 9.210340371976184f / 64.f;
    float ang0 = (float)n * expf(-(float)(2 * p0) * kfac);
    float ang1 = (float)n * expf(-(float)(2 * p1) * kfac);
    float c0 = cosf(ang0), s0 = sinf(ang0);
    float c1 = cosf(ang1), s1 = sinf(ang1);
    bool odd = (lane & 1);
#pragma unroll
    for (int which = 0; which < 2; which++) {
        const float* src = base + which * DIMD;
        float v0 = src[lane], v1 = src[lane + 32];
        float s = v0 + v1, sq = v0 * v0 + v1 * v1;
#pragma unroll
        for (int o = 16; o; o >>= 1) {
            s  += __shfl_xor_sync(0xffffffffu, s,  o);
            sq += __shfl_xor_sync(0xffffffffu, sq, o);
        }
        float mean = s * (1.f / DHD);
        float var  = sq * (1.f / DHD) - mean * mean;
        float rstd = rsqrtf(var + 1e-5f);
        v0 = (v0 - mean) * rstd;
        v1 = (v1 - mean) * rstd;
        float o0 = __shfl_xor_sync(0xffffffffu, v0, 1);
        float o1 = __shfl_xor_sync(0xffffffffu, v1, 1);
        float r0 = odd ? (o0 * s0 + v0 * c0) : (v0 * c0 - o0 * s0);
        float r1 = odd ? (o1 * s1 + v1 * c1) : (v1 * c1 - o1 * s1);
        float* dst = (which == 0) ? qr : kr;
        dst[oo + lane] = r0;
        dst[oo + lane + 32] = r1;
    }
    const float* vsrc = base + 2 * DIMD;
    vr[oo + lane] = vsrc[lane];
    vr[oo + lane + 32] = vsrc[lane + 32];
}

// ---------------- pair bias (windowed only) ----------------
__global__ void pairbias_kernel(const float* __restrict__ pair_rep, const float* __restrict__ wb,
                                float* __restrict__ biasw) {
    __shared__ float wbs[DPR * HH];
    __shared__ float colsum[HH];
    int t = threadIdx.x;
    for (int i = t; i < DPR * HH; i += 128) wbs[i] = wb[i];
    __syncthreads();
    if (t < HH) {
        float cs = 0.f;
        for (int p = 0; p < DPR; p++) cs += wbs[p * HH + t];
        colsum[t] = cs;
    }
    __syncthreads();
    int blk = blockIdx.x;
    int q = blk & 31, w = (blk >> 5) & 15, b = blk >> 9;
    int i = w * NQ + q;
    int idx = w * NQ - 48 + t;
    int j = min(max(idx, 0), NN - 1);
    const float* xr = pair_rep + (((long)b * NN + i) * NN + j) * DPR;
    float s = 0.f, s2 = 0.f;
    float dot[HH];
#pragma unroll
    for (int h = 0; h < HH; h++) dot[h] = 0.f;
#pragma unroll 4
    for (int p = 0; p < DPR; p += 4) {
        float4 xv = *(const float4*)(xr + p);
        s  += xv.x + xv.y + xv.z + xv.w;
        s2 += xv.x * xv.x + xv.y * xv.y + xv.z * xv.z + xv.w * xv.w;
#pragma unroll
        for (int h = 0; h < HH; h++)
            dot[h] += xv.x * wbs[p * HH + h] + xv.y * wbs[(p + 1) * HH + h]
                    + xv.z * wbs[(p + 2) * HH + h] + xv.w * wbs[(p + 3) * HH + h];
    }
    float mean = s * (1.f / DPR);
    float var  = s2 * (1.f / DPR) - mean * mean;
    float rstd = rsqrtf(var + 1e-5f);
    float* outp = biasw + ((long)blk * NK + t) * HH;
#pragma unroll
    for (int h = 0; h < HH; h++) outp[h] = (dot[h] - mean * colsum[h]) * rstd;
}

// ---------------- windowed attention -> og bf16 [hi|lo] ----------------
__global__ __launch_bounds__(256) void attn_kernel(
    const float* __restrict__ qr, const float* __restrict__ kr, const float* __restrict__ vr,
    const float* __restrict__ pair_mask, const float* __restrict__ biasw,
    const float* __restrict__ qkvg, __nv_bfloat16* __restrict__ og_bf) {
    __shared__ float q_s[NQ][DHD];
    __shared__ float kv[64][65];
    __shared__ float sc[NQ][NK];
    int blk = blockIdx.x;
    int w = blk & 15;
    int h = (blk >> 4) % 12;
    int b = blk / 192;
    int t = threadIdx.x;
    long bh = (long)(b * HH + h) * NN * DHD;
    for (int e = t; e < NQ * DHD; e += 256) {
        int qq = e >> 6, d = e & 63;
        q_s[qq][d] = qr[bh + (long)(w * NQ + qq) * DHD + d];
    }
    int qrow = t >> 3, klane = t & 7;
    int iglob = w * NQ + qrow;
    for (int half = 0; half < 2; half++) {
        __syncthreads();
        for (int e = t; e < 64 * 64; e += 256) {
            int d = e & 63, kkl = e >> 6;
            int kk = half * 64 + kkl;
            int jn = min(max(w * NQ - 48 + kk, 0), NN - 1);
            kv[kkl][d] = kr[bh + (long)jn * DHD + d];
        }
        __syncthreads();
#pragma unroll
        for (int jj = 0; jj < 8; jj++) {
            int kkl = klane + jj * 8;
            int kk = half * 64 + kkl;
            float dot = 0.f;
#pragma unroll
            for (int d = 0; d < DHD; d++) dot = fmaf(q_s[qrow][d], kv[kkl][d], dot);
            int idxr = w * NQ - 48 + kk;
            bool valid = (idxr >= 0) && (idxr < NN);
            int jn = min(max(idxr, 0), NN - 1);
            float pm = pair_mask[((long)b * NN + iglob) * NN + jn];
            float bv = biasw[(((long)(b * NWW + w) * NQ + qrow) * NK + kk) * HH + h];
            sc[qrow][kk] = (valid && pm > 0.f) ? (dot * 0.125f + bv) : -1e9f;
        }
    }
    __syncthreads();
    {
        float vals[16];
        float mx = -3.4e38f;
#pragma unroll
        for (int jj = 0; jj < 16; jj++) {
            vals[jj] = sc[qrow][klane + jj * 8];
            mx = fmaxf(mx, vals[jj]);
        }
#pragma unroll
        for (int o = 4; o; o >>= 1) mx = fmaxf(mx, __shfl_xor_sync(0xffffffffu, mx, o));
        float sm = 0.f;
#pragma unroll
        for (int jj = 0; jj < 16; jj++) { vals[jj] = expf(vals[jj] - mx); sm += vals[jj]; }
#pragma unroll
        for (int o = 4; o; o >>= 1) sm += __shfl_xor_sync(0xffffffffu, sm, o);
        float inv = 1.f / sm;
#pragma unroll
        for (int jj = 0; jj < 16; jj++) sc[qrow][klane + jj * 8] = vals[jj] * inv;
    }
    int dgrp = t & 7;
    float outv[8];
#pragma unroll
    for (int jj = 0; jj < 8; jj++) outv[jj] = 0.f;
    for (int half = 0; half < 2; half++) {
        __syncthreads();
        for (int e = t; e < 64 * 64; e += 256) {
            int d = e & 63, kkl = e >> 6;
            int kk = half * 64 + kkl;
            int jn = min(max(w * NQ - 48 + kk, 0), NN - 1);
            kv[kkl][d] = vr[bh + (long)jn * DHD + d];
        }
        __syncthreads();
#pragma unroll 8
        for (int kkl = 0; kkl < 64; kkl++) {
            float a = sc[qrow][half * 64 + kkl];
#pragma unroll
            for (int jj = 0; jj < 8; jj++)
                outv[jj] = fmaf(a, kv[kkl][dgrp + jj * 8], outv[jj]);
        }
    }
    int m = b * NN + iglob;
    const float* gp = qkvg + (long)m * (4 * DIMD) + 3 * DIMD + h * DHD;
    __nv_bfloat16* ob = og_bf + (long)m * (2 * DIMD) + h * DHD;
#pragma unroll
    for (int jj = 0; jj < 8; jj++) {
        int d = dgrp + jj * 8;
        float v = outv[jj] * gp[d];
        __nv_bfloat16 hi, lo; bsplit(v, hi, lo);
        ob[d] = hi; ob[DIMD + d] = lo;
    }
}

// ---------------- weight decompositions (job table), x8 vectorized, [hi|lo] ----------------
#define NJOBS 13
struct DWAll {
    const float* src[NJOBS];
    long dstoff[NJOBS];
    long base8[NJOBS + 1];
    int K[NJOBS], Nmat[NJOBS], Ntot[NJOBS], coloff[NJOBS];
};
__global__ void decomp_w_all_kernel(DWAll p, __nv_bfloat16* __restrict__ bf) {
    long idx8 = (long)blockIdx.x * 256 + threadIdx.x;
    int j = 0;
#pragma unroll
    for (int q = 0; q < NJOBS; q++) if (idx8 >= p.base8[q + 1]) j = q + 1;
    long e = (idx8 - p.base8[j]) * 8;
    int Nm = p.Nmat[j];
    int k = (int)(e / Nm);
    int n = (int)(e - (long)k * Nm);
    const float* sp = p.src[j] + e;
    float4 w0 = *(const float4*)sp;
    float4 w1 = *(const float4*)(sp + 4);
    uint4 hi8, lo8;
    { uint2 h, l; bsplit4(w0, h, l); hi8.x = h.x; hi8.y = h.y; lo8.x = l.x; lo8.y = l.y; }
    { uint2 h, l; bsplit4(w1, h, l); hi8.z = h.x; hi8.w = h.y; lo8.z = l.x; lo8.w = l.y; }
    long Nt = p.Ntot[j];
    long seg = (long)p.K[j] * Nt;
    __nv_bfloat16* d0 = bf + p.dstoff[j] + (long)k * Nt + p.coloff[j] + n;
    *(uint4*)d0         = hi8;
    *(uint4*)(d0 + seg) = lo8;
}

// ---------------- tensor-core GEMM with hi/lo fragment reuse + cp.async ----------------
__device__ __forceinline__ void mma_bf16(float* d, const unsigned* a, const unsigned* b) {
    asm volatile(
        "mma.sync.aligned.m16n8k16.row.col.f32.bf16.bf16.f32 "
        "{%0,%1,%2,%3}, {%4,%5,%6,%7}, {%8,%9}, {%0,%1,%2,%3};"
        : "+f"(d[0]), "+f"(d[1]), "+f"(d[2]), "+f"(d[3])
        : "r"(a[0]), "r"(a[1]), "r"(a[2]), "r"(a[3]), "r"(b[0]), "r"(b[1]));
}
__device__ __forceinline__ void ldsm_x4(unsigned* r, uint32_t addr) {
    asm volatile("ldmatrix.sync.aligned.m8n8.x4.shared.b16 {%0,%1,%2,%3}, [%4];"
                 : "=r"(r[0]), "=r"(r[1]), "=r"(r[2]), "=r"(r[3]) : "r"(addr));
}
__device__ __forceinline__ void ldsm_x4t(unsigned* r, uint32_t addr) {
    asm volatile("ldmatrix.sync.aligned.m8n8.x4.trans.shared.b16 {%0,%1,%2,%3}, [%4];"
                 : "=r"(r[0]), "=r"(r[1]), "=r"(r[2]), "=r"(r[3]) : "r"(addr));
}
__device__ __forceinline__ void cp16(uint32_t dst, const void* src) {
    asm volatile("cp.async.cg.shared.global [%0], [%1], 16;" :: "r"(dst), "l"(src));
}

struct MG {
    const __nv_bfloat16* A; int K;       // A [M][2K] = [hi|lo]
    const __nv_bfloat16* B; int Nld;     // B [2K][Nld], rows [0,K) hi, [K,2K) lo
    float* C; int ldc;
    int M, Ntot;
    const float* biasp[6]; int sig[6]; int multi;
    int splitk;
};

#define KPA 40
#define BPA 136
#define SM_AH 0
#define SM_AL (2*128*KPA)
#define SM_BH (SM_AL + 2*128*KPA)
#define SM_BL (SM_BH + 2*32*BPA)
#define SM_ELEMS (SM_BL + 2*32*BPA)    // 37,888 bf16 = 75,776 B

__global__ void __launch_bounds__(256, 2) mma_gemm_kernel(MG p) {
    extern __shared__ __nv_bfloat16 sm[];
    const int tid = threadIdx.x;
    const int lane = tid & 31, wid = tid >> 5;
    const int wm = wid & 3, wn = wid >> 2;
    const int row0 = blockIdx.y * 128, col0 = blockIdx.x * 128;
    const int Kper = p.K / p.splitk;
    const int k0 = blockIdx.z * Kper;
    const long lda = 2L * p.K;

    const int ar0 = tid >> 2, ac = (tid & 3) * 8;
    const int br0 = tid >> 4, bc = (tid & 15) * 8;
    const __nv_bfloat16* aH0 = p.A + (long)(row0 + ar0) * lda + k0 + ac;
    const __nv_bfloat16* aH1 = aH0 + 64L * lda;
    const __nv_bfloat16* aL0 = aH0 + p.K;
    const __nv_bfloat16* aL1 = aH1 + p.K;
    const long bLoff = (long)p.K * p.Nld;
    const __nv_bfloat16* bH0 = p.B + (long)(k0 + br0) * p.Nld + col0 + bc;
    const __nv_bfloat16* bH1 = bH0 + 16L * p.Nld;
    const __nv_bfloat16* bL0 = bH0 + bLoff;
    const __nv_bfloat16* bL1 = bH1 + bLoff;

    // smem store addresses (fixed per thread, per buffer)
    uint32_t sAh[2], sAl[2], sBh[2], sBl[2];
#pragma unroll
    for (int bfi = 0; bfi < 2; bfi++) {
        sAh[bfi] = (uint32_t)__cvta_generic_to_shared(&sm[SM_AH + (bfi * 128 + ar0) * KPA + ac]);
        sAl[bfi] = (uint32_t)__cvta_generic_to_shared(&sm[SM_AL + (bfi * 128 + ar0) * KPA + ac]);
        sBh[bfi] = (uint32_t)__cvta_generic_to_shared(&sm[SM_BH + (bfi * 32 + br0) * BPA + bc]);
        sBl[bfi] = (uint32_t)__cvta_generic_to_shared(&sm[SM_BL + (bfi * 32 + br0) * BPA + bc]);
    }
    const uint32_t aRow64 = 64u * KPA * 2;   // byte offset for rows +64
    const uint32_t bRow16 = 16u * BPA * 2;   // byte offset for rows +16

    float acc[2][8][4];
#pragma unroll
    for (int i = 0; i < 2; i++)
#pragma unroll
        for (int j = 0; j < 8; j++)
#pragma unroll
            for (int q = 0; q < 4; q++) acc[i][j][q] = 0.f;

    const int nt = Kper / 32;

    auto issue = [&](int t) {
        const int bfi = t & 1;
        long ka = (long)t * 32;
        long kb = (long)t * 32 * p.Nld;
        cp16(sAh[bfi],          aH0 + ka);
        cp16(sAh[bfi] + aRow64, aH1 + ka);
        cp16(sAl[bfi],          aL0 + ka);
        cp16(sAl[bfi] + aRow64, aL1 + ka);
        cp16(sBh[bfi],          bH0 + kb);
        cp16(sBh[bfi] + bRow16, bH1 + kb);
        cp16(sBl[bfi],          bL0 + kb);
        cp16(sBl[bfi] + bRow16, bL1 + kb);
        asm volatile("cp.async.commit_group;");
    };

    issue(0);
    for (int t = 0; t < nt; t++) {
        if (t + 1 < nt) {
            issue(t + 1);
            asm volatile("cp.async.wait_group 1;");
        } else {
            asm volatile("cp.async.wait_group 0;");
        }
        __syncthreads();
        const int bfi = t & 1;
        const __nv_bfloat16* Ahb = &sm[SM_AH + bfi * 128 * KPA];
        const __nv_bfloat16* Alb = &sm[SM_AL + bfi * 128 * KPA];
        const __nv_bfloat16* Bhb = &sm[SM_BH + bfi * 32 * BPA];
        const __nv_bfloat16* Blb = &sm[SM_BL + bfi * 32 * BPA];
#pragma unroll
        for (int ks = 0; ks < 2; ks++) {
            unsigned ah[2][4], al[2][4];
#pragma unroll
            for (int i = 0; i < 2; i++) {
                int r = wm * 32 + i * 16 + (lane & 15);
                int c = ks * 16 + (lane >> 4) * 8;
                ldsm_x4(ah[i], (uint32_t)__cvta_generic_to_shared(Ahb + r * KPA + c));
                ldsm_x4(al[i], (uint32_t)__cvta_generic_to_shared(Alb + r * KPA + c));
            }
            unsigned bfr[8][2];
#pragma unroll
            for (int j = 0; j < 4; j++) {
                uint32_t bd = (uint32_t)__cvta_generic_to_shared(
                    Bhb + (ks * 16 + (lane & 15)) * BPA + wn * 64 + j * 16 + (lane >> 4) * 8);
                unsigned tmp[4];
                ldsm_x4t(tmp, bd);
                bfr[2 * j][0]     = tmp[0]; bfr[2 * j][1]     = tmp[1];
                bfr[2 * j + 1][0] = tmp[2]; bfr[2 * j + 1][1] = tmp[3];
            }
#pragma unroll
            for (int i = 0; i < 2; i++)
#pragma unroll
                for (int j = 0; j < 8; j++) {
                    mma_bf16(acc[i][j], ah[i], bfr[j]);
                    mma_bf16(acc[i][j], al[i], bfr[j]);
                }
            // b_lo: reuse bfr registers
#pragma unroll
            for (int j = 0; j < 4; j++) {
                uint32_t bd = (uint32_t)__cvta_generic_to_shared(
                    Blb + (ks * 16 + (lane & 15)) * BPA + wn * 64 + j * 16 + (lane >> 4) * 8);
                unsigned tmp[4];
                ldsm_x4t(tmp, bd);
                bfr[2 * j][0]     = tmp[0]; bfr[2 * j][1]     = tmp[1];
                bfr[2 * j + 1][0] = tmp[2]; bfr[2 * j + 1][1] = tmp[3];
            }
#pragma unroll
            for (int i = 0; i < 2; i++)
#pragma unroll
                for (int j = 0; j < 8; j++)
                    mma_bf16(acc[i][j], ah[i], bfr[j]);
        }
        __syncthreads();
    }

    const int rbase = row0 + wm * 32 + (lane >> 2);
    const int cbase = col0 + wn * 64 + (lane & 3) * 2;
    if (p.splitk > 1) {
        float* Cp = p.C + (long)blockIdx.z * p.M * p.Ntot;
#pragma unroll
        for (int i = 0; i < 2; i++)
#pragma unroll
            for (int j = 0; j < 8; j++) {
                int r = rbase + i * 16, c = cbase + j * 8;
                *(float2*)(Cp + (long)r * p.Ntot + c)       = make_float2(acc[i][j][0], acc[i][j][1]);
                *(float2*)(Cp + (long)(r + 8) * p.Ntot + c) = make_float2(acc[i][j][2], acc[i][j][3]);
            }
    } else {
        int wblk = p.multi ? (col0 / 768) : 0;
        const float* bias = p.biasp[wblk];
        int dosig = p.sig[wblk];
        int noff = wblk * 768;
#pragma unroll
        for (int i = 0; i < 2; i++)
#pragma unroll
            for (int j = 0; j < 8; j++) {
                int r = rbase + i * 16, c = cbase + j * 8;
                float b0 = bias ? bias[c - noff] : 0.f;
                float b1 = bias ? bias[c + 1 - noff] : 0.f;
                float z0 = acc[i][j][0] + b0, z1 = acc[i][j][1] + b1;
                float z2 = acc[i][j][2] + b0, z3 = acc[i][j][3] + b1;
                if (dosig) { z0 = sigf(z0); z1 = sigf(z1); z2 = sigf(z2); z3 = sigf(z3); }
                *(float2*)(p.C + (long)r * p.ldc + c)       = make_float2(z0, z1);
                *(float2*)(p.C + (long)(r + 8) * p.ldc + c) = make_float2(z2, z3);
            }
    }
}

// ---------------- hidden = a * silu(g) -> bf16 [hi|lo] ----------------
__global__ void silu_decomp_kernel(const float* __restrict__ ab, __nv_bfloat16* __restrict__ out) {
    long i = (long)blockIdx.x * 256 + threadIdx.x;
    int m = (int)(i / (INR / 4));
    int c4 = (int)(i % (INR / 4)) * 4;
    float4 a = *(const float4*)(ab + (long)m * (2 * INR) + c4);
    float4 g = *(const float4*)(ab + (long)m * (2 * INR) + INR + c4);
    float4 hv;
    hv.x = a.x * g.x * sigf(g.x);
    hv.y = a.y * g.y * sigf(g.y);
    hv.z = a.z * g.z * sigf(g.z);
    hv.w = a.w * g.w * sigf(g.w);
    uint2 hi4, lo4; bsplit4(hv, hi4, lo4);
    __nv_bfloat16* d0 = out + (long)m * (2 * INR) + c4;
    *(uint2*)d0         = hi4;
    *(uint2*)(d0 + INR) = lo4;
}

// ---------------- fused: split-K reduce (wo) + scale1 + residual + adaln2 + decompose ----------------
__global__ void reduce_adaln_kernel(const float* __restrict__ part,
                                    const float* __restrict__ bias,
                                    const float* __restrict__ sig1,
                                    const float* __restrict__ g2,
                                    const float* __restrict__ b2,
                                    const float* __restrict__ xm,
                                    const float* __restrict__ mask,
                                    float* __restrict__ x1_out,
                                    __nv_bfloat16* __restrict__ xt_bf) {
    int m = blockIdx.x, t = threadIdx.x;
    float mk = mask[m];
    const long MN = (long)MROWS * DIMD;
    float v[3];
#pragma unroll
    for (int c = 0; c < 3; c++) {
        int n = t + c * 256;
        long idx = (long)m * DIMD + n;
        float z = part[idx] + part[MN + idx] + part[2 * MN + idx] + bias[n];
        float s = sig1[(long)m * (6 * DIMD) + n];
        float x1 = (z * s * mk * mk + xm[idx]) * mk;
        x1_out[idx] = x1;
        v[c] = x1;
    }
    float s = 0.f, s2 = 0.f;
#pragma unroll
    for (int c = 0; c < 3; c++) { s += v[c]; s2 += v[c] * v[c]; }
    float2 r = block_reduce2_256(s, s2);
    float mean = r.x * (1.f / DIMD);
    float var  = r.y * (1.f / DIMD) - mean * mean;
    float rstd = rsqrtf(var + 1e-5f);
    __nv_bfloat16* ob = xt_bf + (long)m * (2 * DIMD);
#pragma unroll
    for (int c = 0; c < 3; c++) {
        int j = t + c * 256;
        float g = g2[(long)m * (6 * DIMD) + j];
        float b = b2[(long)m * (6 * DIMD) + j];
        float val = ((v[c] - mean) * rstd * g + b) * mk;
        __nv_bfloat16 hi, lo; bsplit(val, hi, lo);
        ob[j] = hi; ob[DIMD + j] = lo;
    }
}

// ---------------- final split-K reduce + epilogue ----------------
__global__ void reduce_epi_kernel(const float* __restrict__ part,
                                  const float* __restrict__ e1, int e1ld,
                                  const float* __restrict__ e2,
                                  const float* __restrict__ mask,
                                  float* __restrict__ C) {
    int m = blockIdx.x, t = threadIdx.x;
    float mk = mask[m];
    const long MN = (long)MROWS * DIMD;
#pragma unroll
    for (int c = 0; c < 3; c++) {
        int n = t + c * 256;
        long idx = (long)m * DIMD + n;
        float z = part[idx] + part[MN + idx] + part[2 * MN + idx];
        float s = e1[(long)m * e1ld + n];
        float t0 = z * mk;
        float t1 = t0 * s * mk * mk;
        C[idx] = ((t1 + e2[idx]) * mk) * mk;
    }
}

// ---------------- host launch ----------------
static void fill_jobs(DWAll& d, const float* const* srcs, const long* dsto,
                      const int* Ks, const int* Nm, const int* Nt, const int* Co,
                      int njobs, long& acc) {
    acc = 0;
    for (int j = 0; j < njobs; j++) {
        d.src[j] = srcs[j]; d.dstoff[j] = dsto[j];
        d.K[j] = Ks[j]; d.Nmat[j] = Nm[j]; d.Ntot[j] = Nt[j]; d.coloff[j] = Co[j];
        d.base8[j] = acc;
        acc += (long)Ks[j] * Nm[j] / 8;
    }
    for (int j = njobs; j <= NJOBS; j++) d.base8[j] = acc;
    for (int j = njobs; j < NJOBS; j++) {
        d.src[j] = srcs[njobs - 1]; d.dstoff[j] = dsto[njobs - 1];
        d.K[j] = Ks[njobs - 1]; d.Nmat[j] = Nm[njobs - 1];
        d.Ntot[j] = Nt[njobs - 1]; d.coloff[j] = Co[njobs - 1];
    }
}

extern "C" void kernel_launch(void* const* d_in, const int* in_sizes, int n_in,
                              void* d_out, int out_size) {
    const float* x         = (const float*)d_in[0];
    const float* pair_rep  = (const float*)d_in[1];
    const float* cond      = (const float*)d_in[2];
    const float* mask      = (const float*)d_in[3];
    const float* pair_mask = (const float*)d_in[4];
    const float* adaln1_gw = (const float*)d_in[5];
    const float* adaln1_gb = (const float*)d_in[6];
    const float* adaln1_bw = (const float*)d_in[7];
    const float* wq = (const float*)d_in[8],  *bq = (const float*)d_in[9];
    const float* wk = (const float*)d_in[10], *bk = (const float*)d_in[11];
    const float* wv = (const float*)d_in[12], *bv = (const float*)d_in[13];
    const float* wg = (const float*)d_in[14], *bg = (const float*)d_in[15];
    const float* wb_pair = (const float*)d_in[16];
    const float* wo = (const float*)d_in[17], *bo = (const float*)d_in[18];
    const float* scale1_w = (const float*)d_in[19], *scale1_b = (const float*)d_in[20];
    const float* adaln2_gw = (const float*)d_in[21], *adaln2_gb = (const float*)d_in[22];
    const float* adaln2_bw = (const float*)d_in[23];
    const float* tr_win  = (const float*)d_in[24];
    const float* tr_wout = (const float*)d_in[25];
    const float* scale2_w = (const float*)d_in[26], *scale2_b = (const float*)d_in[27];

    float* S = nullptr;
    cudaGetSymbolAddress((void**)&S, g_scratch);
    __nv_bfloat16* BF = nullptr;
    cudaGetSymbolAddress((void**)&BF, g_bf);

    float* cond_out = S + OFF_COND;
    float* xm       = S + OFF_XM;
    float* qkvg     = S + OFF_QKVG;
    float* qr       = S + OFF_QR;
    float* kr       = S + OFF_KR;
    float* vr       = S + OFF_VR;
    float* biasw    = S + OFF_BIAS;
    float* x1       = S + OFF_X1;
    float* ab       = S + OFF_AB;
    float* part     = S + OFF_PART;

    static int smem_set = 0;
    const int SMEM_BYTES = SM_ELEMS * 2;
    if (!smem_set) {
        cudaFuncSetAttribute(mma_gemm_kernel, cudaFuncAttributeMaxDynamicSharedMemorySize, SMEM_BYTES);
        smem_set = 1;
    }

    // (1) early weight decomposition (cond projections + qkvg)
    {
        DWAll d = {};
        const float* srcs[10] = { adaln1_gw, adaln1_bw, scale1_w, adaln2_gw, adaln2_bw, scale2_w,
                                  wq, wk, wv, wg };
        long  dsto[10] = { W2COND, W2COND, W2COND, W2COND, W2COND, W2COND,
                           W2QKVG, W2QKVG, W2QKVG, W2QKVG };
        int   Ks[10]   = { DCND, DCND, DCND, DCND, DCND, DCND, DIMD, DIMD, DIMD, DIMD };
        int   Nm[10]   = { DIMD, DIMD, DIMD, DIMD, DIMD, DIMD, DIMD, DIMD, DIMD, DIMD };
        int   Nt[10]   = { 6 * DIMD, 6 * DIMD, 6 * DIMD, 6 * DIMD, 6 * DIMD, 6 * DIMD,
                           4 * DIMD, 4 * DIMD, 4 * DIMD, 4 * DIMD };
        int   Co[10]   = { 0, DIMD, 2 * DIMD, 3 * DIMD, 4 * DIMD, 5 * DIMD,
                           0, DIMD, 2 * DIMD, 3 * DIMD };
        long acc;
        fill_jobs(d, srcs, dsto, Ks, Nm, Nt, Co, 10, acc);
        decomp_w_all_kernel<<<(int)(acc / 256), 256>>>(d, BF);
    }

    // (2) LN(cond) -> bf16 [hi|lo]
    ln_cond_kernel<<<MROWS, 256>>>(cond, BF + A2CN);

    // (3) late weight decomposition (wo, tr_win, tr_wout)
    {
        DWAll d = {};
        const float* srcs[3] = { wo, tr_win, tr_wout };
        long  dsto[3] = { W2WO, W2TRIN, W2TROUT };
        int   Ks[3]   = { DIMD, DIMD, INR };
        int   Nm[3]   = { DIMD, 2 * INR, DIMD };
        int   Nt[3]   = { DIMD, 2 * INR, DIMD };
        int   Co[3]   = { 0, 0, 0 };
        long acc;
        fill_jobs(d, srcs, dsto, Ks, Nm, Nt, Co, 3, acc);
        decomp_w_all_kernel<<<(int)(acc / 256), 256>>>(d, BF);
    }

    // (4) six cond projections in one tensor GEMM  <-- ncu capture target
    {
        MG p = {};
        p.A = BF + A2CN; p.K = DCND;
        p.B = BF + W2COND; p.Nld = 6 * DIMD;
        p.C = cond_out; p.ldc = 6 * DIMD; p.M = MROWS; p.Ntot = 6 * DIMD;
        p.biasp[0] = adaln1_gb; p.biasp[1] = nullptr; p.biasp[2] = scale1_b;
        p.biasp[3] = adaln2_gb; p.biasp[4] = nullptr; p.biasp[5] = scale2_b;
        p.sig[0] = 1; p.sig[1] = 0; p.sig[2] = 1; p.sig[3] = 1; p.sig[4] = 0; p.sig[5] = 1;
        p.multi = 1; p.splitk = 1;
        mma_gemm_kernel<<<dim3((6 * DIMD) / 128, MROWS / 128, 1), 256, SMEM_BYTES>>>(p);
    }

    // (5) pair bias
    pairbias_kernel<<<BB * NWW * NQ, 128>>>(pair_rep, wb_pair, biasw);

    // (6) xa = adaln1(x) -> bf16 [hi|lo] (+ xm)
    adaln_kernel<<<MROWS, 256>>>(x, mask, cond_out, cond_out + DIMD, xm, BF + A2XA);

    // (7) QKVG tensor GEMM
    {
        MG p = {};
        p.A = BF + A2XA; p.K = DIMD;
        p.B = BF + W2QKVG; p.Nld = 4 * DIMD;
        p.C = qkvg; p.ldc = 4 * DIMD; p.M = MROWS; p.Ntot = 4 * DIMD;
        p.biasp[0] = bq; p.biasp[1] = bk; p.biasp[2] = bv; p.biasp[3] = bg;
        p.sig[0] = 0; p.sig[1] = 0; p.sig[2] = 0; p.sig[3] = 1;
        p.multi = 1; p.splitk = 1;
        mma_gemm_kernel<<<dim3((4 * DIMD) / 128, MROWS / 128, 1), 256, SMEM_BYTES>>>(p);
    }

    // (8) rope
    qkrope_kernel<<<MROWS, 384>>>(qkvg, qr, kr, vr);

    // (9) attention
    attn_kernel<<<BB * HH * NWW, 256>>>(qr, kr, vr, pair_mask, biasw, qkvg, BF + A2OG);

    // (10) wo GEMM split-K=3 -> partials; fused reduce + scale1 + residual + adaln2 + decompose
    {
        MG p = {};
        p.A = BF + A2OG; p.K = DIMD;
        p.B = BF + W2WO; p.Nld = DIMD;
        p.C = part; p.ldc = DIMD; p.M = MROWS; p.Ntot = DIMD;
        p.multi = 0; p.splitk = 3;
        mma_gemm_kernel<<<dim3(DIMD / 128, MROWS / 128, 3), 256, SMEM_BYTES>>>(p);
        reduce_adaln_kernel<<<MROWS, 256>>>(part, bo,
                                            cond_out + 2 * DIMD, cond_out + 3 * DIMD,
                                            cond_out + 4 * DIMD, xm, mask, x1, BF + A2XT);
    }

    // (11) merged transition-in [a|g] tensor GEMM
    {
        MG p = {};
        p.A = BF + A2XT; p.K = DIMD;
        p.B = BF + W2TRIN; p.Nld = 2 * INR;
        p.C = ab; p.ldc = 2 * INR; p.M = MROWS; p.Ntot = 2 * INR;
        p.multi = 0; p.splitk = 1;
        mma_gemm_kernel<<<dim3((2 * INR) / 128, MROWS / 128, 1), 256, SMEM_BYTES>>>(p);
    }
    // (12) hidden = a * silu(g) -> bf16 [hi|lo]
    silu_decomp_kernel<<<(int)((long)MROWS * INR / 4 / 256), 256>>>(ab, BF + A2AB);

    // (13) transition-out split-K=3 + reduce+epilogue -> d_out
    {
        MG p = {};
        p.A = BF + A2AB; p.K = INR;
        p.B = BF + W2TROUT; p.Nld = DIMD;
        p.C = part; p.ldc = DIMD; p.M = MROWS; p.Ntot = DIMD;
        p.multi = 0; p.splitk = 3;
        mma_gemm_kernel<<<dim3(DIMD / 128, MROWS / 128, 3), 256, SMEM_BYTES>>>(p);
        reduce_epi_kernel<<<MROWS, 256>>>(part, cond_out + 5 * DIMD, 6 * DIMD,
                                          x1, mask, (float*)d_out);
    }
}